// round 11
// baseline (speedup 1.0000x reference)
#include <cuda_runtime.h>
#include <math.h>
#include <stdint.h>

// ---------------- problem constants ----------------
constexpr int kB  = 8;
constexpr int kT  = 1024;
constexpr int kL  = 4;
constexpr int kI  = 4;
constexpr int kN  = 1032;
constexpr int kH  = 768;
constexpr int kHe = 4;
constexpr int kDh = 192;
constexpr int kM  = kB * kN;        // 8256
constexpr int kMp = 8320;           // 65*128
constexpr int kNCH = 16;
constexpr int kSPAN = 65;
constexpr int kCk = kH / 16;        // 48 K-chunks of 16
constexpr int kChunkF = 2048;       // floats per 128x16 chunk block

// ---------------- scratch ----------------
__device__ float g_h  [kMp * kH];
__device__ float g_haf[65 * kCk * kChunkF];        // A, tf32-rounded, fragment-major
__device__ float g_wbf[3 * 6 * kCk * kChunkF];     // W^T, tf32-rounded, fragment-major
__device__ float g_hw [kMp * kH];
__device__ float4 g_esp[6 * kMp];                  // per-(ntile,row) partials {es0,es1,ed0,ed1}
__device__ float g_es [kM * kHe];
__device__ float g_ed [kM * kHe];
__device__ float g_wtail[kB * kN * 32];
__device__ float g_tpart[kB * kNCH * 8 * kH];
__device__ unsigned char g_mlab[kB * kT];
__device__ unsigned char g_mimg[kB * kT];

__device__ __forceinline__ float wredsum(float v){
#pragma unroll
    for (int o = 16; o > 0; o >>= 1) v += __shfl_xor_sync(0xffffffffu, v, o);
    return v;
}
__device__ __forceinline__ float wredmax(float v){
#pragma unroll
    for (int o = 16; o > 0; o >>= 1) v = fmaxf(v, __shfl_xor_sync(0xffffffffu, v, o));
    return v;
}
__device__ __forceinline__ float f2tf_f(float x){
    uint32_t u; asm("cvt.rna.tf32.f32 %0, %1;" : "=r"(u) : "f"(x));
    return __uint_as_float(u);
}
__device__ __forceinline__ void cp16(uint32_t dst, const void* src){
    asm volatile("cp.async.cg.shared.global [%0], [%1], 16;" :: "r"(dst), "l"(src));
}

// fragment-major A index
__device__ __forceinline__ int haf_idx(int row, int d){
    int tile = row >> 7, m = row & 127;
    int g = m >> 4, rr = m & 15, r = rr & 7, p = rr >> 3;
    int ck = d >> 4, dd = d & 15;
    int h = dd >> 3, q = dd & 7, c = q & 3, chi = q >> 2;
    int slot = (h * 4 + c) ^ ((r & 1) << 2);
    return (tile * kCk + ck) * kChunkF + ((g * 8 + r) * 8 + slot) * 4 + chi * 2 + p;
}
// fragment-major B index (128-N tiles)
__device__ __forceinline__ int wbf_idx(int li, int n, int k){
    int ntile = n >> 7, nn = n & 127;
    int ck = k >> 4, dd = k & 15, c = dd & 3, j = dd >> 2;
    return ((li * 6 + ntile) * kCk + ck) * kChunkF + (nn * 4 + c) * 4 + j;
}

__device__ __forceinline__ void mma_tf32(float* c, const float4& a, float b0, float b1){
    asm volatile(
        "mma.sync.aligned.m16n8k8.row.col.f32.tf32.tf32.f32 "
        "{%0,%1,%2,%3}, {%4,%5,%6,%7}, {%8,%9}, {%0,%1,%2,%3};\n"
        : "+f"(c[0]), "+f"(c[1]), "+f"(c[2]), "+f"(c[3])
        : "r"(__float_as_uint(a.x)), "r"(__float_as_uint(a.y)),
          "r"(__float_as_uint(a.z)), "r"(__float_as_uint(a.w)),
          "r"(__float_as_uint(b0)), "r"(__float_as_uint(b1)));
}

// ---------------- 0. W -> transposed, tf32-rounded, fragment-major ----------------
__global__ __launch_bounds__(256) void k_wprep(const float* __restrict__ W){
    __shared__ float ts[32][33];
    int li = blockIdx.z;
    int k0 = blockIdx.x * 32, n0 = blockIdx.y * 32;
    int x = threadIdx.x & 31, y0 = threadIdx.x >> 5;
    const float* Wp = W + (size_t)li * kH * kH;
    for (int yy = y0; yy < 32; yy += 8)
        ts[yy][x] = Wp[(size_t)(k0 + yy) * kH + n0 + x];
    __syncthreads();
    for (int yy = y0; yy < 32; yy += 8)
        g_wbf[wbf_idx(li, n0 + yy, k0 + x)] = f2tf_f(ts[x][yy]);
}

// ---------------- 1. assemble x ----------------
__global__ __launch_bounds__(256) void k_init(const float* __restrict__ txt,
                                              const float* __restrict__ lab,
                                              const float* __restrict__ img){
    int i = blockIdx.x * 256 + threadIdx.x;
    if (i >= kM * kH) return;
    int row = i / kH, d = i % kH;
    int b = row / kN, n = row % kN;
    float v;
    if (n < kT)            v = txt[(size_t)(b * kT + n) * kH + d];
    else if (n < kT + kL)  v = lab[(size_t)(b * kL + (n - kT)) * kH + d];
    else                   v = img[(size_t)(b * kI + (n - kT - kL)) * kH + d];
    g_h  [(size_t)row * kH + d] = v;
    g_haf[haf_idx(row, d)] = f2tf_f(v);
}

// ---------------- 2. top-3-of-4 cosine masks ----------------
__global__ __launch_bounds__(256) void k_topk(const float* __restrict__ txt,
                                              const float* __restrict__ lab,
                                              const float* __restrict__ img){
    int gw   = (blockIdx.x * 256 + threadIdx.x) >> 5;
    int lane = threadIdx.x & 31;
    if (gw >= kB * kT) return;
    int b = gw / kT, t = gw % kT;
    const float* tp = txt + (size_t)(b * kT + t) * kH;
    float tn = 0.f;
    float dl[4] = {0,0,0,0}, nl[4] = {0,0,0,0};
    float di[4] = {0,0,0,0}, ni[4] = {0,0,0,0};
    for (int j = lane; j < kH; j += 32){
        float tv = tp[j];
        tn += tv * tv;
#pragma unroll
        for (int c = 0; c < 4; c++){
            float lv = lab[(size_t)(b * kL + c) * kH + j];
            dl[c] += tv * lv;  nl[c] += lv * lv;
            float iv = img[(size_t)(b * kI + c) * kH + j];
            di[c] += tv * iv;  ni[c] += iv * iv;
        }
    }
    tn = wredsum(tn);
#pragma unroll
    for (int c = 0; c < 4; c++){
        dl[c] = wredsum(dl[c]); nl[c] = wredsum(nl[c]);
        di[c] = wredsum(di[c]); ni[c] = wredsum(ni[c]);
    }
    if (lane == 0){
        float st = sqrtf(tn);
        float sl[4], si[4];
#pragma unroll
        for (int c = 0; c < 4; c++){
            sl[c] = dl[c] / fmaxf(st * sqrtf(nl[c]), 1e-8f);
            si[c] = di[c] / fmaxf(st * sqrtf(ni[c]), 1e-8f);
        }
        int bl = 0, bi = 0;
#pragma unroll
        for (int c = 1; c < 4; c++){
            if (sl[c] <= sl[bl]) bl = c;
            if (si[c] <= si[bi]) bi = c;
        }
        g_mlab[b * kT + t] = (unsigned char)(0xF ^ (1 << bl));
        g_mimg[b * kT + t] = (unsigned char)(0xF ^ (1 << bi));
    }
}

// ---------------- 3. tf32 GEMM + fused es/ed partial epilogue (R10) ----------------
constexpr int kStages = 4;
constexpr int kSmemFloats = kStages * kChunkF * 2 + 256 + 1024;
constexpr int kSmemBytes  = kSmemFloats * 4;       // 70656

__device__ __forceinline__ void fill_stage(uint32_t asB, uint32_t bsB,
                                           const float* Ac, const float* Bc, int tid){
#pragma unroll
    for (int i = 0; i < 2; i++){
        int c = tid + i * 256;
        cp16(asB + c * 16, Ac + c * 4);
        cp16(bsB + c * 16, Bc + c * 4);
    }
}

__global__ __launch_bounds__(256, 2) void k_gemm(int li, const float* __restrict__ asv,
                                                 const float* __restrict__ adv){
    extern __shared__ float sm[];
    float* As   = sm;
    float* Bs   = sm + kStages * kChunkF;
    float* as_s = sm + 2 * kStages * kChunkF;
    float* ad_s = as_s + 128;
    float4* sred = (float4*)(ad_s + 128);
    int tid  = threadIdx.x;
    int warp = tid >> 5, lane = tid & 31;
    int wr = warp & 3, wc = warp >> 2;
    int grp = lane >> 2, thr4 = lane & 3;
    const float* Ag = g_haf + (size_t)blockIdx.x * kCk * kChunkF;
    const float* Bg = g_wbf + (size_t)(li * 6 + blockIdx.y) * kCk * kChunkF;

    if (tid < 128){
        as_s[tid] = asv[blockIdx.y * 128 + tid];
        ad_s[tid] = adv[blockIdx.y * 128 + tid];
    }

    float acc[2][8][4];
#pragma unroll
    for (int mt = 0; mt < 2; mt++)
#pragma unroll
        for (int nt = 0; nt < 8; nt++)
#pragma unroll
            for (int i = 0; i < 4; i++) acc[mt][nt][i] = 0.f;

    uint32_t asBase = (uint32_t)__cvta_generic_to_shared(As);
    uint32_t bsBase = (uint32_t)__cvta_generic_to_shared(Bs);

#pragma unroll
    for (int s = 0; s < 3; s++){
        fill_stage(asBase + s * kChunkF * 4, bsBase + s * kChunkF * 4,
                   Ag + s * kChunkF, Bg + s * kChunkF, tid);
        asm volatile("cp.async.commit_group;");
    }

    int aidx[2][2];
#pragma unroll
    for (int mt = 0; mt < 2; mt++){
        int g = wr * 2 + mt;
#pragma unroll
        for (int h = 0; h < 2; h++)
            aidx[mt][h] = (g * 8 + grp) * 8 + ((h * 4 + thr4) ^ ((grp & 1) << 2));
    }
    int bidx0 = (wc * 64 + grp) * 4 + thr4;   // + nt*32

    for (int ck = 0; ck < kCk; ++ck){
        asm volatile("cp.async.wait_group 2;");
        __syncthreads();
        if (ck + 3 < kCk){
            int s = (ck + 3) & 3;
            fill_stage(asBase + s * kChunkF * 4, bsBase + s * kChunkF * 4,
                       Ag + (ck + 3) * kChunkF, Bg + (ck + 3) * kChunkF, tid);
            asm volatile("cp.async.commit_group;");
        } else {
            asm volatile("cp.async.commit_group;");
        }
        int st = ck & 3;
        const float4* Af = (const float4*)(As + st * kChunkF);
        const float4* Bf = (const float4*)(Bs + st * kChunkF);

        float4 a4[2][2];
#pragma unroll
        for (int mt = 0; mt < 2; mt++)
#pragma unroll
            for (int h = 0; h < 2; h++)
                a4[mt][h] = Af[aidx[mt][h]];
#pragma unroll
        for (int nt = 0; nt < 8; nt++){
            float4 b4 = Bf[bidx0 + nt * 32];
            mma_tf32(acc[0][nt], a4[0][0], b4.x, b4.y);
            mma_tf32(acc[1][nt], a4[1][0], b4.x, b4.y);
            mma_tf32(acc[0][nt], a4[0][1], b4.z, b4.w);
            mma_tf32(acc[1][nt], a4[1][1], b4.z, b4.w);
        }
    }

    // C store
#pragma unroll
    for (int mt = 0; mt < 2; mt++){
        int r = blockIdx.x * 128 + wr * 32 + mt * 16 + grp;
#pragma unroll
        for (int nt = 0; nt < 8; nt++){
            int cg = blockIdx.y * 128 + wc * 64 + nt * 8 + thr4 * 2;
            *(float2*)&g_hw[(size_t)r * kH + cg]       = make_float2(acc[mt][nt][0], acc[mt][nt][1]);
            *(float2*)&g_hw[(size_t)(r + 8) * kH + cg] = make_float2(acc[mt][nt][2], acc[mt][nt][3]);
        }
    }

    // fused es/ed partials
    int hl = (blockIdx.y * 128) / kDh;
    float pes[2][2][2] = {}, ped[2][2][2] = {};
#pragma unroll
    for (int mt = 0; mt < 2; mt++)
#pragma unroll
        for (int nt = 0; nt < 8; nt++){
            int cl = wc * 64 + nt * 8 + thr4 * 2;
            int head = (blockIdx.y * 128 + cl) / kDh;
            int bk = (head == hl) ? 0 : 1;
            float a0 = as_s[cl], a1 = as_s[cl + 1];
            float d0 = ad_s[cl], d1 = ad_s[cl + 1];
            pes[mt][0][bk] += acc[mt][nt][0] * a0 + acc[mt][nt][1] * a1;
            ped[mt][0][bk] += acc[mt][nt][0] * d0 + acc[mt][nt][1] * d1;
            pes[mt][1][bk] += acc[mt][nt][2] * a0 + acc[mt][nt][3] * a1;
            ped[mt][1][bk] += acc[mt][nt][2] * d0 + acc[mt][nt][3] * d1;
        }
#pragma unroll
    for (int mt = 0; mt < 2; mt++)
#pragma unroll
        for (int rh = 0; rh < 2; rh++)
#pragma unroll
            for (int bk = 0; bk < 2; bk++){
#pragma unroll
                for (int o = 1; o < 4; o <<= 1){
                    pes[mt][rh][bk] += __shfl_xor_sync(0xffffffffu, pes[mt][rh][bk], o);
                    ped[mt][rh][bk] += __shfl_xor_sync(0xffffffffu, ped[mt][rh][bk], o);
                }
            }
    if (thr4 == 0){
#pragma unroll
        for (int mt = 0; mt < 2; mt++)
#pragma unroll
            for (int rh = 0; rh < 2; rh++)
                sred[((((wc * 4 + wr) * 2 + mt) * 2 + rh) * 8) + grp] =
                    make_float4(pes[mt][rh][0], pes[mt][rh][1], ped[mt][rh][0], ped[mt][rh][1]);
    }
    __syncthreads();
    if (tid < 128){
        int twr = tid >> 5, tmt = (tid >> 4) & 1, trh = (tid >> 3) & 1, tgrp = tid & 7;
        float4 v0 = sred[((((0 * 4 + twr) * 2 + tmt) * 2 + trh) * 8) + tgrp];
        float4 v1 = sred[((((1 * 4 + twr) * 2 + tmt) * 2 + trh) * 8) + tgrp];
        float4 o = make_float4(v0.x + v1.x, v0.y + v1.y, v0.z + v1.z, v0.w + v1.w);
        g_esp[blockIdx.y * kMp + blockIdx.x * 128 + tid] = o;
    }
}

// ---------------- 3b. reduce es/ed partials across 6 N-tiles ----------------
__global__ __launch_bounds__(256) void k_esred(){
    int row = blockIdx.x * 256 + threadIdx.x;
    if (row >= kM) return;
    const int hlA[6] = {0,0,1,2,2,3};
    const int hhA[6] = {0,1,1,2,3,3};
    float es[4] = {0,0,0,0}, ed[4] = {0,0,0,0};
#pragma unroll
    for (int ty = 0; ty < 6; ty++){
        float4 v = g_esp[ty * kMp + row];
        es[hlA[ty]] += v.x; es[hhA[ty]] += v.y;
        ed[hlA[ty]] += v.z; ed[hhA[ty]] += v.w;
    }
    *(float4*)&g_es[row * kHe] = make_float4(es[0], es[1], es[2], es[3]);
    *(float4*)&g_ed[row * kHe] = make_float4(ed[0], ed[1], ed[2], ed[3]);
}

// ---------------- 5. tail softmax weights ----------------
__global__ __launch_bounds__(256) void k_tail_alpha(){
    __shared__ float ws[kN * 4];
    __shared__ float wr_[8][4];
    __shared__ float m4[4], z4[4];
    int b = blockIdx.x >> 3, q = blockIdx.x & 7;
    int tid = threadIdx.x, lane = tid & 31, wid = tid >> 5;
    int rowbase = b * kN;
    int rowdst  = rowbase + kT + q;
    float edd[4];
#pragma unroll
    for (int h = 0; h < 4; h++) edd[h] = g_ed[rowdst * kHe + h];

    float ml[4] = {-1e30f,-1e30f,-1e30f,-1e30f};
    for (int s = tid; s < kN; s += 256){
        bool inc;
        if (s < kT){
            unsigned mk = (q < 4) ? g_mlab[b * kT + s] : g_mimg[b * kT + s];
            inc = (mk >> (q & 3)) & 1;
        } else inc = true;
        if (inc){
            const float* ep = g_es + (size_t)(rowbase + s) * kHe;
#pragma unroll
            for (int h = 0; h < 4; h++){
                float e = ep[h] + edd[h];
                e = (e >= 0.f) ? e : 0.2f * e;
                ml[h] = fmaxf(ml[h], e);
            }
        }
    }
#pragma unroll
    for (int h = 0; h < 4; h++) ml[h] = wredmax(ml[h]);
    if (lane == 0){
#pragma unroll
        for (int h = 0; h < 4; h++) wr_[wid][h] = ml[h];
    }
    __syncthreads();
    if (tid < 4){
        float mm = -1e30f;
#pragma unroll
        for (int w = 0; w < 8; w++) mm = fmaxf(mm, wr_[w][tid]);
        m4[tid] = mm;
    }
    __syncthreads();

    float zl[4] = {0,0,0,0};
    for (int s = tid; s < kN; s += 256){
        bool inc;
        if (s < kT){
            unsigned mk = (q < 4) ? g_mlab[b * kT + s] : g_mimg[b * kT + s];
            inc = (mk >> (q & 3)) & 1;
        } else inc = true;
        if (inc){
            const float* ep = g_es + (size_t)(rowbase + s) * kHe;
#pragma unroll
            for (int h = 0; h < 4; h++){
                float e = ep[h] + edd[h];
                e = (e >= 0.f) ? e : 0.2f * e;
                float w = expf(e - m4[h]);
                ws[s * 4 + h] = w; zl[h] += w;
            }
        } else {
#pragma unroll
            for (int h = 0; h < 4; h++) ws[s * 4 + h] = 0.f;
        }
    }
#pragma unroll
    for (int h = 0; h < 4; h++) zl[h] = wredsum(zl[h]);
    if (lane == 0){
#pragma unroll
        for (int h = 0; h < 4; h++) wr_[wid][h] = zl[h];
    }
    __syncthreads();
    if (tid < 4){
        float ss = 0.f;
#pragma unroll
        for (int w = 0; w < 8; w++) ss += wr_[w][tid];
        z4[tid] = ss;
    }
    __syncthreads();

    float inv[4];
#pragma unroll
    for (int h = 0; h < 4; h++) inv[h] = 1.0f / z4[h];
    for (int s = tid; s < kN; s += 256){
#pragma unroll
        for (int h = 0; h < 4; h++)
            g_wtail[(size_t)(rowbase + s) * 32 + h * 8 + q] = ws[s * 4 + h] * inv[h];
    }
}

// ---------------- 6. tail aggregation partials ----------------
__global__ __launch_bounds__(256) void k_agg_tailm(){
    __shared__ float sw[kSPAN * 8];
    int b = blockIdx.x, h = blockIdx.y, ch = blockIdx.z;
    int s0 = ch * kSPAN;
    int cnt = min(kSPAN, kN - s0);
    int tid = threadIdx.x;
    for (int i = tid; i < cnt * 8; i += 256){
        int si = i >> 3, qq = i & 7;
        sw[i] = g_wtail[(size_t)(b * kN + s0 + si) * 32 + h * 8 + qq];
    }
    __syncthreads();
    if (tid < kDh){
        float acc[8] = {0,0,0,0,0,0,0,0};
        const float* hp = g_hw + (size_t)(b * kN + s0) * kH + h * kDh + tid;
#pragma unroll 4
        for (int si = 0; si < cnt; si++){
            float hv = hp[(size_t)si * kH];
            float4 w0 = *(const float4*)&sw[si * 8];
            float4 w1 = *(const float4*)&sw[si * 8 + 4];
            acc[0] += w0.x * hv; acc[1] += w0.y * hv;
            acc[2] += w0.z * hv; acc[3] += w0.w * hv;
            acc[4] += w1.x * hv; acc[5] += w1.y * hv;
            acc[6] += w1.z * hv; acc[7] += w1.w * hv;
        }
#pragma unroll
        for (int q = 0; q < 8; q++)
            g_tpart[(size_t)(((b * kNCH + ch) * 8) + q) * kH + h * kDh + tid] = acc[q];
    }
}

// ---------------- 7. text aggregate: 4 dst rows per block + LN ----------------
__global__ __launch_bounds__(256) void k_agg_text_ln(const float* __restrict__ bias,
                                                     const float* __restrict__ gam,
                                                     const float* __restrict__ bet,
                                                     float* __restrict__ outp, int finalFlag){
    __shared__ int   s_src[4][9];
    __shared__ int   s_cnt[4];
    __shared__ float s_e[4][36], s_al[4][36];
    __shared__ float s_m[4][4], s_inv[4][4];
    __shared__ float rs[8], rs2[8];
    __shared__ float s_mu, s_rstd;
    int blk = blockIdx.x;
    int b = blk >> 8, t0 = (blk & 255) * 4;
    int tid = threadIdx.x;

    if (tid < 4){
        int j = tid, t = t0 + j;
        int cnt = 0;
        s_src[j][cnt++] = t;
        if (t > 0)      s_src[j][cnt++] = t - 1;
        if (t < kT - 1) s_src[j][cnt++] = t + 1;
        unsigned ml = g_mlab[b * kT + t], mi = g_mimg[b * kT + t];
#pragma unroll
        for (int c = 0; c < 4; c++) if ((ml >> c) & 1) s_src[j][cnt++] = kT + c;
#pragma unroll
        for (int c = 0; c < 4; c++) if ((mi >> c) & 1) s_src[j][cnt++] = kT + kL + c;
        s_cnt[j] = cnt;
    }
    __syncthreads();
    if (tid < 144){
        int j = tid / 36, r = tid % 36, i = r >> 2, h = r & 3;
        if (i < s_cnt[j]){
            float e = g_es[(size_t)(b * kN + s_src[j][i]) * kHe + h]
                    + g_ed[(size_t)(b * kN + t0 + j) * kHe + h];
            e = (e >= 0.f) ? e : 0.2f * e;
            s_e[j][r] = e;
        }
    }
    __syncthreads();
    if (tid < 16){
        int j = tid >> 2, h = tid & 3;
        float m = -1e30f;
        int cnt = s_cnt[j];
        for (int i = 0; i < cnt; i++) m = fmaxf(m, s_e[j][i * 4 + h]);
        s_m[j][h] = m;
    }
    __syncthreads();
    if (tid < 144){
        int j = tid / 36, r = tid % 36, i = r >> 2, h = r & 3;
        if (i < s_cnt[j]) s_al[j][r] = expf(s_e[j][r] - s_m[j][h]);
    }
    __syncthreads();
    if (tid < 16){
        int j = tid >> 2, h = tid & 3;
        float z = 0.f;
        int cnt = s_cnt[j];
        for (int i = 0; i < cnt; i++) z += s_al[j][i * 4 + h];
        s_inv[j][h] = 1.0f / z;
    }
    __syncthreads();
    if (tid < 144){
        int j = tid / 36, r = tid % 36, i = r >> 2, h = r & 3;
        if (i < s_cnt[j]) s_al[j][r] *= s_inv[j][h];
    }
    __syncthreads();

    int lane = tid & 31, wid = tid >> 5;
    for (int j = 0; j < 4; j++){
        int t = t0 + j;
        int rowdst = b * kN + t;
        int cnt = s_cnt[j];
        float v[3]; float s = 0.f, s2 = 0.f;
#pragma unroll
        for (int rep = 0; rep < 3; rep++){
            int d = tid + rep * 256;
            int head = d / kDh;
            float a = 0.f;
            for (int i = 0; i < cnt; i++)
                a += s_al[j][i * 4 + head] * g_hw[(size_t)(b * kN + s_src[j][i]) * kH + d];
            a += bias[d];
            a = fmaxf(a, 0.f);
            a += g_h[(size_t)rowdst * kH + d];
            v[rep] = a; s += a; s2 += a * a;
        }
        s = wredsum(s); s2 = wredsum(s2);
        if (lane == 0){ rs[wid] = s; rs2[wid] = s2; }
        __syncthreads();
        if (tid == 0){
            float ts = 0.f, ts2 = 0.f;
#pragma unroll
            for (int w = 0; w < 8; w++){ ts += rs[w]; ts2 += rs2[w]; }
            float mu = ts / kH;
            float var = ts2 / kH - mu * mu;
            s_mu = mu; s_rstd = rsqrtf(var + 1e-5f);
        }
        __syncthreads();
        float mu = s_mu, rstd = s_rstd;
#pragma unroll
        for (int rep = 0; rep < 3; rep++){
            int d = tid + rep * 256;
            float y = (v[rep] - mu) * rstd * gam[d] + bet[d];
            if (finalFlag){
                outp[(size_t)(b * kT + t) * kH + d] = y;
            } else {
                g_h  [(size_t)rowdst * kH + d] = y;
                g_haf[haf_idx(rowdst, d)] = f2tf_f(y);
            }
        }
    }
}

// ---------------- 8. tail rows: reduce partials + LN ----------------
__global__ __launch_bounds__(256) void k_tail_ln(const float* __restrict__ bias,
                                                 const float* __restrict__ gam,
                                                 const float* __restrict__ bet){
    int b = blockIdx.x >> 3, q = blockIdx.x & 7;
    int row = b * kN + kT + q;
    int tid = threadIdx.x, lane = tid & 31, wid = tid >> 5;
    __shared__ float rs[8], rs2[8];
    __shared__ float s_mu, s_rstd;
    float v[3]; float s = 0.f, s2 = 0.f;
#pragma unroll
    for (int rep = 0; rep < 3; rep++){
        int d = tid + rep * 256;
        float a = 0.f;
#pragma unroll
        for (int ch = 0; ch < kNCH; ch++)
            a += g_tpart[(size_t)(((b * kNCH + ch) * 8) + q) * kH + d];
        a += bias[d];
        a = fmaxf(a, 0.f);
        a += g_h[(size_t)row * kH + d];
        v[rep] = a; s += a; s2 += a * a;
    }
    s = wredsum(s); s2 = wredsum(s2);
    if (lane == 0){ rs[wid] = s; rs2[wid] = s2; }
    __syncthreads();
    if (tid == 0){
        float ts = 0.f, ts2 = 0.f;
#pragma unroll
        for (int w = 0; w < 8; w++){ ts += rs[w]; ts2 += rs2[w]; }
        float mu = ts / kH;
        float var = ts2 / kH - mu * mu;
        s_mu = mu; s_rstd = rsqrtf(var + 1e-5f);
    }
    __syncthreads();
    float mu = s_mu, rstd = s_rstd;
#pragma unroll
    for (int rep = 0; rep < 3; rep++){
        int d = tid + rep * 256;
        float y = (v[rep] - mu) * rstd * gam[d] + bet[d];
        g_h  [(size_t)row * kH + d] = y;
        g_haf[haf_idx(row, d)] = f2tf_f(y);
    }
}

// ---------------- launch ----------------
extern "C" void kernel_launch(void* const* d_in, const int* in_sizes, int n_in,
                              void* d_out, int out_size){
    const float* txt  = (const float*)d_in[0];
    const float* lab  = (const float*)d_in[1];
    const float* img  = (const float*)d_in[2];
    const float* W    = (const float*)d_in[3];
    const float* as   = (const float*)d_in[4];
    const float* ad   = (const float*)d_in[5];
    const float* bias = (const float*)d_in[6];
    const float* lng  = (const float*)d_in[7];
    const float* lnb  = (const float*)d_in[8];
    float* out = (float*)d_out;

    static bool attrDone = false;
    if (!attrDone){
        cudaFuncSetAttribute(k_gemm, cudaFuncAttributeMaxDynamicSharedMemorySize, kSmemBytes);
        attrDone = true;
    }

    k_wprep<<<dim3(kH / 32, kH / 32, 3), 256>>>(W);
    k_init<<<(kM * kH + 255) / 256, 256>>>(txt, lab, img);
    k_topk<<<(kB * kT) / 8, 256>>>(txt, lab, img);

    for (int li = 0; li < 3; li++){
        k_gemm<<<dim3(kMp / 128, kH / 128), 256, kSmemBytes>>>(li, as + li * kH, ad + li * kH);
        k_esred<<<(kM + 255) / 256, 256>>>();
        if (li < 2){
            k_tail_alpha<<<kB * 8, 256>>>();
            k_agg_tailm<<<dim3(kB, kHe, kNCH), 256>>>();
        }
        k_agg_text_ln<<<kB * kT / 4, 256>>>(bias + li * kH, lng + li * kH, lnb + li * kH,
                                            out, li == 2 ? 1 : 0);
        if (li < 2)
            k_tail_ln<<<kB * 8, 256>>>(bias + li * kH, lng + li * kH, lnb + li * kH);
    }
}

// round 12
// speedup vs baseline: 1.0384x; 1.0384x over previous
#include <cuda_runtime.h>
#include <math.h>
#include <stdint.h>

// ---------------- problem constants ----------------
constexpr int kB  = 8;
constexpr int kT  = 1024;
constexpr int kL  = 4;
constexpr int kI  = 4;
constexpr int kN  = 1032;
constexpr int kH  = 768;
constexpr int kHe = 4;
constexpr int kDh = 192;
constexpr int kM  = kB * kN;        // 8256
constexpr int kMp = 8320;           // 65*128
constexpr int kNCH = 16;
constexpr int kSPAN = 65;
constexpr int kCk = kH / 16;        // 48 K-chunks of 16
constexpr int kChunkF = 2048;       // floats per 128x16 chunk block
constexpr int kTC = 16;             // text t's per streaming block

// ---------------- scratch ----------------
__device__ float g_h  [kMp * kH];
__device__ float g_haf[65 * kCk * kChunkF];        // A, tf32-rounded, fragment-major
__device__ float g_wbf[3 * 6 * kCk * kChunkF];     // W^T, tf32-rounded, fragment-major
__device__ float g_hw [kMp * kH];
__device__ float4 g_esp[6 * kMp];                  // per-(ntile,row) es/ed partials
__device__ float g_es [kM * kHe];
__device__ float g_ed [kM * kHe];
__device__ float g_wtext[kB * kT * kHe * 12];      // 11 alphas + pad per (b,t,h)
__device__ float g_wtail[kB * kN * 32];
__device__ float g_tpart[kB * kNCH * 8 * kH];
__device__ unsigned char g_mlab[kB * kT];
__device__ unsigned char g_mimg[kB * kT];

__device__ __forceinline__ float wredsum(float v){
#pragma unroll
    for (int o = 16; o > 0; o >>= 1) v += __shfl_xor_sync(0xffffffffu, v, o);
    return v;
}
__device__ __forceinline__ float wredmax(float v){
#pragma unroll
    for (int o = 16; o > 0; o >>= 1) v = fmaxf(v, __shfl_xor_sync(0xffffffffu, v, o));
    return v;
}
__device__ __forceinline__ float f2tf_f(float x){
    uint32_t u; asm("cvt.rna.tf32.f32 %0, %1;" : "=r"(u) : "f"(x));
    return __uint_as_float(u);
}
__device__ __forceinline__ void cp16(uint32_t dst, const void* src){
    asm volatile("cp.async.cg.shared.global [%0], [%1], 16;" :: "r"(dst), "l"(src));
}

// fragment-major A index
__device__ __forceinline__ int haf_idx(int row, int d){
    int tile = row >> 7, m = row & 127;
    int g = m >> 4, rr = m & 15, r = rr & 7, p = rr >> 3;
    int ck = d >> 4, dd = d & 15;
    int h = dd >> 3, q = dd & 7, c = q & 3, chi = q >> 2;
    int slot = (h * 4 + c) ^ ((r & 1) << 2);
    return (tile * kCk + ck) * kChunkF + ((g * 8 + r) * 8 + slot) * 4 + chi * 2 + p;
}
// fragment-major B index (128-N tiles)
__device__ __forceinline__ int wbf_idx(int li, int n, int k){
    int ntile = n >> 7, nn = n & 127;
    int ck = k >> 4, dd = k & 15, c = dd & 3, j = dd >> 2;
    return ((li * 6 + ntile) * kCk + ck) * kChunkF + (nn * 4 + c) * 4 + j;
}

__device__ __forceinline__ void mma_tf32(float* c, const float4& a, float b0, float b1){
    asm volatile(
        "mma.sync.aligned.m16n8k8.row.col.f32.tf32.tf32.f32 "
        "{%0,%1,%2,%3}, {%4,%5,%6,%7}, {%8,%9}, {%0,%1,%2,%3};\n"
        : "+f"(c[0]), "+f"(c[1]), "+f"(c[2]), "+f"(c[3])
        : "r"(__float_as_uint(a.x)), "r"(__float_as_uint(a.y)),
          "r"(__float_as_uint(a.z)), "r"(__float_as_uint(a.w)),
          "r"(__float_as_uint(b0)), "r"(__float_as_uint(b1)));
}

// ---------------- 0. W -> transposed, tf32-rounded, fragment-major ----------------
__global__ __launch_bounds__(256) void k_wprep(const float* __restrict__ W){
    __shared__ float ts[32][33];
    int li = blockIdx.z;
    int k0 = blockIdx.x * 32, n0 = blockIdx.y * 32;
    int x = threadIdx.x & 31, y0 = threadIdx.x >> 5;
    const float* Wp = W + (size_t)li * kH * kH;
    for (int yy = y0; yy < 32; yy += 8)
        ts[yy][x] = Wp[(size_t)(k0 + yy) * kH + n0 + x];
    __syncthreads();
    for (int yy = y0; yy < 32; yy += 8)
        g_wbf[wbf_idx(li, n0 + yy, k0 + x)] = f2tf_f(ts[x][yy]);
}

// ---------------- 1. assemble x ----------------
__global__ __launch_bounds__(256) void k_init(const float* __restrict__ txt,
                                              const float* __restrict__ lab,
                                              const float* __restrict__ img){
    int i = blockIdx.x * 256 + threadIdx.x;
    if (i >= kM * kH) return;
    int row = i / kH, d = i % kH;
    int b = row / kN, n = row % kN;
    float v;
    if (n < kT)            v = txt[(size_t)(b * kT + n) * kH + d];
    else if (n < kT + kL)  v = lab[(size_t)(b * kL + (n - kT)) * kH + d];
    else                   v = img[(size_t)(b * kI + (n - kT - kL)) * kH + d];
    g_h  [(size_t)row * kH + d] = v;
    g_haf[haf_idx(row, d)] = f2tf_f(v);
}

// ---------------- 2. top-3-of-4 cosine masks ----------------
__global__ __launch_bounds__(256) void k_topk(const float* __restrict__ txt,
                                              const float* __restrict__ lab,
                                              const float* __restrict__ img){
    int gw   = (blockIdx.x * 256 + threadIdx.x) >> 5;
    int lane = threadIdx.x & 31;
    if (gw >= kB * kT) return;
    int b = gw / kT, t = gw % kT;
    const float* tp = txt + (size_t)(b * kT + t) * kH;
    float tn = 0.f;
    float dl[4] = {0,0,0,0}, nl[4] = {0,0,0,0};
    float di[4] = {0,0,0,0}, ni[4] = {0,0,0,0};
    for (int j = lane; j < kH; j += 32){
        float tv = tp[j];
        tn += tv * tv;
#pragma unroll
        for (int c = 0; c < 4; c++){
            float lv = lab[(size_t)(b * kL + c) * kH + j];
            dl[c] += tv * lv;  nl[c] += lv * lv;
            float iv = img[(size_t)(b * kI + c) * kH + j];
            di[c] += tv * iv;  ni[c] += iv * iv;
        }
    }
    tn = wredsum(tn);
#pragma unroll
    for (int c = 0; c < 4; c++){
        dl[c] = wredsum(dl[c]); nl[c] = wredsum(nl[c]);
        di[c] = wredsum(di[c]); ni[c] = wredsum(ni[c]);
    }
    if (lane == 0){
        float st = sqrtf(tn);
        float sl[4], si[4];
#pragma unroll
        for (int c = 0; c < 4; c++){
            sl[c] = dl[c] / fmaxf(st * sqrtf(nl[c]), 1e-8f);
            si[c] = di[c] / fmaxf(st * sqrtf(ni[c]), 1e-8f);
        }
        int bl = 0, bi = 0;
#pragma unroll
        for (int c = 1; c < 4; c++){
            if (sl[c] <= sl[bl]) bl = c;
            if (si[c] <= si[bi]) bi = c;
        }
        g_mlab[b * kT + t] = (unsigned char)(0xF ^ (1 << bl));
        g_mimg[b * kT + t] = (unsigned char)(0xF ^ (1 << bi));
    }
}

// ---------------- 3. tf32 GEMM + fused es/ed partial epilogue (R10) ----------------
constexpr int kStages = 4;
constexpr int kSmemFloats = kStages * kChunkF * 2 + 256 + 1024;
constexpr int kSmemBytes  = kSmemFloats * 4;       // 70656

__device__ __forceinline__ void fill_stage(uint32_t asB, uint32_t bsB,
                                           const float* Ac, const float* Bc, int tid){
#pragma unroll
    for (int i = 0; i < 2; i++){
        int c = tid + i * 256;
        cp16(asB + c * 16, Ac + c * 4);
        cp16(bsB + c * 16, Bc + c * 4);
    }
}

__global__ __launch_bounds__(256, 2) void k_gemm(int li, const float* __restrict__ asv,
                                                 const float* __restrict__ adv){
    extern __shared__ float sm[];
    float* As   = sm;
    float* Bs   = sm + kStages * kChunkF;
    float* as_s = sm + 2 * kStages * kChunkF;
    float* ad_s = as_s + 128;
    float4* sred = (float4*)(ad_s + 128);
    int tid  = threadIdx.x;
    int warp = tid >> 5, lane = tid & 31;
    int wr = warp & 3, wc = warp >> 2;
    int grp = lane >> 2, thr4 = lane & 3;
    const float* Ag = g_haf + (size_t)blockIdx.x * kCk * kChunkF;
    const float* Bg = g_wbf + (size_t)(li * 6 + blockIdx.y) * kCk * kChunkF;

    if (tid < 128){
        as_s[tid] = asv[blockIdx.y * 128 + tid];
        ad_s[tid] = adv[blockIdx.y * 128 + tid];
    }

    float acc[2][8][4];
#pragma unroll
    for (int mt = 0; mt < 2; mt++)
#pragma unroll
        for (int nt = 0; nt < 8; nt++)
#pragma unroll
            for (int i = 0; i < 4; i++) acc[mt][nt][i] = 0.f;

    uint32_t asBase = (uint32_t)__cvta_generic_to_shared(As);
    uint32_t bsBase = (uint32_t)__cvta_generic_to_shared(Bs);

#pragma unroll
    for (int s = 0; s < 3; s++){
        fill_stage(asBase + s * kChunkF * 4, bsBase + s * kChunkF * 4,
                   Ag + s * kChunkF, Bg + s * kChunkF, tid);
        asm volatile("cp.async.commit_group;");
    }

    int aidx[2][2];
#pragma unroll
    for (int mt = 0; mt < 2; mt++){
        int g = wr * 2 + mt;
#pragma unroll
        for (int h = 0; h < 2; h++)
            aidx[mt][h] = (g * 8 + grp) * 8 + ((h * 4 + thr4) ^ ((grp & 1) << 2));
    }
    int bidx0 = (wc * 64 + grp) * 4 + thr4;   // + nt*32

    for (int ck = 0; ck < kCk; ++ck){
        asm volatile("cp.async.wait_group 2;");
        __syncthreads();
        if (ck + 3 < kCk){
            int s = (ck + 3) & 3;
            fill_stage(asBase + s * kChunkF * 4, bsBase + s * kChunkF * 4,
                       Ag + (ck + 3) * kChunkF, Bg + (ck + 3) * kChunkF, tid);
            asm volatile("cp.async.commit_group;");
        } else {
            asm volatile("cp.async.commit_group;");
        }
        int st = ck & 3;
        const float4* Af = (const float4*)(As + st * kChunkF);
        const float4* Bf = (const float4*)(Bs + st * kChunkF);

        float4 a4[2][2];
#pragma unroll
        for (int mt = 0; mt < 2; mt++)
#pragma unroll
            for (int h = 0; h < 2; h++)
                a4[mt][h] = Af[aidx[mt][h]];
#pragma unroll
        for (int nt = 0; nt < 8; nt++){
            float4 b4 = Bf[bidx0 + nt * 32];
            mma_tf32(acc[0][nt], a4[0][0], b4.x, b4.y);
            mma_tf32(acc[1][nt], a4[1][0], b4.x, b4.y);
            mma_tf32(acc[0][nt], a4[0][1], b4.z, b4.w);
            mma_tf32(acc[1][nt], a4[1][1], b4.z, b4.w);
        }
    }

    // C store
#pragma unroll
    for (int mt = 0; mt < 2; mt++){
        int r = blockIdx.x * 128 + wr * 32 + mt * 16 + grp;
#pragma unroll
        for (int nt = 0; nt < 8; nt++){
            int cg = blockIdx.y * 128 + wc * 64 + nt * 8 + thr4 * 2;
            *(float2*)&g_hw[(size_t)r * kH + cg]       = make_float2(acc[mt][nt][0], acc[mt][nt][1]);
            *(float2*)&g_hw[(size_t)(r + 8) * kH + cg] = make_float2(acc[mt][nt][2], acc[mt][nt][3]);
        }
    }

    // fused es/ed partials
    int hl = (blockIdx.y * 128) / kDh;
    float pes[2][2][2] = {}, ped[2][2][2] = {};
#pragma unroll
    for (int mt = 0; mt < 2; mt++)
#pragma unroll
        for (int nt = 0; nt < 8; nt++){
            int cl = wc * 64 + nt * 8 + thr4 * 2;
            int head = (blockIdx.y * 128 + cl) / kDh;
            int bk = (head == hl) ? 0 : 1;
            float a0 = as_s[cl], a1 = as_s[cl + 1];
            float d0 = ad_s[cl], d1 = ad_s[cl + 1];
            pes[mt][0][bk] += acc[mt][nt][0] * a0 + acc[mt][nt][1] * a1;
            ped[mt][0][bk] += acc[mt][nt][0] * d0 + acc[mt][nt][1] * d1;
            pes[mt][1][bk] += acc[mt][nt][2] * a0 + acc[mt][nt][3] * a1;
            ped[mt][1][bk] += acc[mt][nt][2] * d0 + acc[mt][nt][3] * d1;
        }
#pragma unroll
    for (int mt = 0; mt < 2; mt++)
#pragma unroll
        for (int rh = 0; rh < 2; rh++)
#pragma unroll
            for (int bk = 0; bk < 2; bk++){
#pragma unroll
                for (int o = 1; o < 4; o <<= 1){
                    pes[mt][rh][bk] += __shfl_xor_sync(0xffffffffu, pes[mt][rh][bk], o);
                    ped[mt][rh][bk] += __shfl_xor_sync(0xffffffffu, ped[mt][rh][bk], o);
                }
            }
    if (thr4 == 0){
#pragma unroll
        for (int mt = 0; mt < 2; mt++)
#pragma unroll
            for (int rh = 0; rh < 2; rh++)
                sred[((((wc * 4 + wr) * 2 + mt) * 2 + rh) * 8) + grp] =
                    make_float4(pes[mt][rh][0], pes[mt][rh][1], ped[mt][rh][0], ped[mt][rh][1]);
    }
    __syncthreads();
    if (tid < 128){
        int twr = tid >> 5, tmt = (tid >> 4) & 1, trh = (tid >> 3) & 1, tgrp = tid & 7;
        float4 v0 = sred[((((0 * 4 + twr) * 2 + tmt) * 2 + trh) * 8) + tgrp];
        float4 v1 = sred[((((1 * 4 + twr) * 2 + tmt) * 2 + trh) * 8) + tgrp];
        float4 o = make_float4(v0.x + v1.x, v0.y + v1.y, v0.z + v1.z, v0.w + v1.w);
        g_esp[blockIdx.y * kMp + blockIdx.x * 128 + tid] = o;
    }
}

// ---------------- 3b. reduce es/ed partials across 6 N-tiles ----------------
__global__ __launch_bounds__(256) void k_esred(){
    int row = blockIdx.x * 256 + threadIdx.x;
    if (row >= kM) return;
    const int hlA[6] = {0,0,1,2,2,3};
    const int hhA[6] = {0,1,1,2,3,3};
    float es[4] = {0,0,0,0}, ed[4] = {0,0,0,0};
#pragma unroll
    for (int ty = 0; ty < 6; ty++){
        float4 v = g_esp[ty * kMp + row];
        es[hlA[ty]] += v.x; es[hhA[ty]] += v.y;
        ed[hlA[ty]] += v.z; ed[hhA[ty]] += v.w;
    }
    *(float4*)&g_es[row * kHe] = make_float4(es[0], es[1], es[2], es[3]);
    *(float4*)&g_ed[row * kHe] = make_float4(ed[0], ed[1], ed[2], ed[3]);
}

// ---------------- 4. text alphas: dense 11-slot per (b,t,h) ----------------
__global__ __launch_bounds__(256) void k_text_alpha(){
    int gid = blockIdx.x * 256 + threadIdx.x;
    if (gid >= kB * kT * kHe) return;
    int h = gid & 3, t = (gid >> 2) % kT, b = gid / (kT * kHe);
    int base = b * kN;
    float edd = g_ed[(size_t)(base + t) * kHe + h];
    unsigned ml = g_mlab[b * kT + t], mi = g_mimg[b * kT + t];

    float e[11]; bool inc[11];
    e[0] = g_es[(size_t)(base + t) * kHe + h];               inc[0] = true;
    e[1] = (t > 0)      ? g_es[(size_t)(base + t - 1) * kHe + h] : 0.f;  inc[1] = (t > 0);
    e[2] = (t < kT - 1) ? g_es[(size_t)(base + t + 1) * kHe + h] : 0.f;  inc[2] = (t < kT - 1);
#pragma unroll
    for (int c = 0; c < 4; c++){
        e[3 + c] = g_es[(size_t)(base + kT + c) * kHe + h];       inc[3 + c] = (ml >> c) & 1;
        e[7 + c] = g_es[(size_t)(base + kT + kL + c) * kHe + h];  inc[7 + c] = (mi >> c) & 1;
    }
    float m = -1e30f;
#pragma unroll
    for (int i = 0; i < 11; i++){
        float v = e[i] + edd;
        v = (v >= 0.f) ? v : 0.2f * v;
        e[i] = v;
        if (inc[i]) m = fmaxf(m, v);
    }
    float w[11]; float z = 0.f;
#pragma unroll
    for (int i = 0; i < 11; i++){
        w[i] = inc[i] ? expf(e[i] - m) : 0.f;
        z += w[i];
    }
    float invz = 1.0f / z;
    float* op = g_wtext + (size_t)gid * 12;
#pragma unroll
    for (int i = 0; i < 11; i++) op[i] = w[i] * invz;
    op[11] = 0.f;
}

// ---------------- 5. tail softmax weights ----------------
__global__ __launch_bounds__(256) void k_tail_alpha(){
    __shared__ float ws[kN * 4];
    __shared__ float wr_[8][4];
    __shared__ float m4[4], z4[4];
    int b = blockIdx.x >> 3, q = blockIdx.x & 7;
    int tid = threadIdx.x, lane = tid & 31, wid = tid >> 5;
    int rowbase = b * kN;
    int rowdst  = rowbase + kT + q;
    float edd[4];
#pragma unroll
    for (int h = 0; h < 4; h++) edd[h] = g_ed[rowdst * kHe + h];

    float ml[4] = {-1e30f,-1e30f,-1e30f,-1e30f};
    for (int s = tid; s < kN; s += 256){
        bool inc;
        if (s < kT){
            unsigned mk = (q < 4) ? g_mlab[b * kT + s] : g_mimg[b * kT + s];
            inc = (mk >> (q & 3)) & 1;
        } else inc = true;
        if (inc){
            const float* ep = g_es + (size_t)(rowbase + s) * kHe;
#pragma unroll
            for (int h = 0; h < 4; h++){
                float e = ep[h] + edd[h];
                e = (e >= 0.f) ? e : 0.2f * e;
                ml[h] = fmaxf(ml[h], e);
            }
        }
    }
#pragma unroll
    for (int h = 0; h < 4; h++) ml[h] = wredmax(ml[h]);
    if (lane == 0){
#pragma unroll
        for (int h = 0; h < 4; h++) wr_[wid][h] = ml[h];
    }
    __syncthreads();
    if (tid < 4){
        float mm = -1e30f;
#pragma unroll
        for (int w = 0; w < 8; w++) mm = fmaxf(mm, wr_[w][tid]);
        m4[tid] = mm;
    }
    __syncthreads();

    float zl[4] = {0,0,0,0};
    for (int s = tid; s < kN; s += 256){
        bool inc;
        if (s < kT){
            unsigned mk = (q < 4) ? g_mlab[b * kT + s] : g_mimg[b * kT + s];
            inc = (mk >> (q & 3)) & 1;
        } else inc = true;
        if (inc){
            const float* ep = g_es + (size_t)(rowbase + s) * kHe;
#pragma unroll
            for (int h = 0; h < 4; h++){
                float e = ep[h] + edd[h];
                e = (e >= 0.f) ? e : 0.2f * e;
                float w = expf(e - m4[h]);
                ws[s * 4 + h] = w; zl[h] += w;
            }
        } else {
#pragma unroll
            for (int h = 0; h < 4; h++) ws[s * 4 + h] = 0.f;
        }
    }
#pragma unroll
    for (int h = 0; h < 4; h++) zl[h] = wredsum(zl[h]);
    if (lane == 0){
#pragma unroll
        for (int h = 0; h < 4; h++) wr_[wid][h] = zl[h];
    }
    __syncthreads();
    if (tid < 4){
        float ss = 0.f;
#pragma unroll
        for (int w = 0; w < 8; w++) ss += wr_[w][tid];
        z4[tid] = ss;
    }
    __syncthreads();

    float inv[4];
#pragma unroll
    for (int h = 0; h < 4; h++) inv[h] = 1.0f / z4[h];
    for (int s = tid; s < kN; s += 256){
#pragma unroll
        for (int h = 0; h < 4; h++)
            g_wtail[(size_t)(rowbase + s) * 32 + h * 8 + q] = ws[s * 4 + h] * inv[h];
    }
}

// ---------------- 6. tail aggregation partials ----------------
__global__ __launch_bounds__(256) void k_agg_tailm(){
    __shared__ float sw[kSPAN * 8];
    int b = blockIdx.x, h = blockIdx.y, ch = blockIdx.z;
    int s0 = ch * kSPAN;
    int cnt = min(kSPAN, kN - s0);
    int tid = threadIdx.x;
    for (int i = tid; i < cnt * 8; i += 256){
        int si = i >> 3, qq = i & 7;
        sw[i] = g_wtail[(size_t)(b * kN + s0 + si) * 32 + h * 8 + qq];
    }
    __syncthreads();
    if (tid < kDh){
        float acc[8] = {0,0,0,0,0,0,0,0};
        const float* hp = g_hw + (size_t)(b * kN + s0) * kH + h * kDh + tid;
#pragma unroll 4
        for (int si = 0; si < cnt; si++){
            float hv = hp[(size_t)si * kH];
            float4 w0 = *(const float4*)&sw[si * 8];
            float4 w1 = *(const float4*)&sw[si * 8 + 4];
            acc[0] += w0.x * hv; acc[1] += w0.y * hv;
            acc[2] += w0.z * hv; acc[3] += w0.w * hv;
            acc[4] += w1.x * hv; acc[5] += w1.y * hv;
            acc[6] += w1.z * hv; acc[7] += w1.w * hv;
        }
#pragma unroll
        for (int q = 0; q < 8; q++)
            g_tpart[(size_t)(((b * kNCH + ch) * 8) + q) * kH + h * kDh + tid] = acc[q];
    }
}

// ---------------- 7. text streaming aggregate + LN (768 threads, window) ----------------
__global__ __launch_bounds__(768) void k_agg_text_ln(const float* __restrict__ bias,
                                                     const float* __restrict__ gam,
                                                     const float* __restrict__ bet,
                                                     float* __restrict__ outp, int finalFlag){
    __shared__ float rs[24], rs2[24];
    __shared__ float s_mu, s_rstd;
    int b = blockIdx.x, t0 = blockIdx.y * kTC;
    int d = threadIdx.x, tid = threadIdx.x;
    int lane = tid & 31, wid = tid >> 5;
    int head = d / kDh;
    int base = b * kN;

    float bi = bias[d], gm = gam[d], bt = bet[d];
    float tailv[8];
#pragma unroll
    for (int c = 0; c < 8; c++)
        tailv[c] = g_hw[(size_t)(base + kT + c) * kH + d];

    float prev = (t0 > 0) ? g_hw[(size_t)(base + t0 - 1) * kH + d] : 0.f;
    float cur  = g_hw[(size_t)(base + t0) * kH + d];
    float nxt  = g_hw[(size_t)(base + t0 + 1) * kH + d];   // t0+1 <= kT-15 < kT always
    float resid = g_h[(size_t)(base + t0) * kH + d];

    for (int j = 0; j < kTC; j++){
        int t = t0 + j;
        // prefetch next iteration's data before barriers
        float nxt2 = 0.f, resid2 = 0.f;
        if (j + 1 < kTC){
            if (t + 2 < kT) nxt2 = g_hw[(size_t)(base + t + 2) * kH + d];
            resid2 = g_h[(size_t)(base + t + 1) * kH + d];
        }
        const float4* al4 = (const float4*)(g_wtext + (size_t)(((b * kT + t) * kHe) + head) * 12);
        float4 a0 = al4[0], a1 = al4[1], a2 = al4[2];

        float a = a0.x * cur + a0.y * prev + a0.z * nxt;
        a += a0.w * tailv[0] + a1.x * tailv[1] + a1.y * tailv[2] + a1.z * tailv[3];
        a += a1.w * tailv[4] + a2.x * tailv[5] + a2.y * tailv[6] + a2.z * tailv[7];
        a += bi;
        a = fmaxf(a, 0.f);
        a += resid;

        float s = wredsum(a), s2 = wredsum(a * a);
        if (lane == 0){ rs[wid] = s; rs2[wid] = s2; }
        __syncthreads();
        if (tid == 0){
            float ts = 0.f, ts2 = 0.f;
#pragma unroll
            for (int w = 0; w < 24; w++){ ts += rs[w]; ts2 += rs2[w]; }
            float mu = ts / kH;
            float var = ts2 / kH - mu * mu;
            s_mu = mu; s_rstd = rsqrtf(var + 1e-5f);
        }
        __syncthreads();
        float y = (a - s_mu) * s_rstd * gm + bt;
        int rowdst = base + t;
        if (finalFlag){
            outp[(size_t)(b * kT + t) * kH + d] = y;
        } else {
            g_h  [(size_t)rowdst * kH + d] = y;
            g_haf[haf_idx(rowdst, d)] = f2tf_f(y);
        }
        prev = cur; cur = nxt; nxt = nxt2; resid = resid2;
    }
}

// ---------------- 8. tail rows: reduce partials + LN ----------------
__global__ __launch_bounds__(256) void k_tail_ln(const float* __restrict__ bias,
                                                 const float* __restrict__ gam,
                                                 const float* __restrict__ bet){
    int b = blockIdx.x >> 3, q = blockIdx.x & 7;
    int row = b * kN + kT + q;
    int tid = threadIdx.x, lane = tid & 31, wid = tid >> 5;
    __shared__ float rs[8], rs2[8];
    __shared__ float s_mu, s_rstd;
    float v[3]; float s = 0.f, s2 = 0.f;
#pragma unroll
    for (int rep = 0; rep < 3; rep++){
        int d = tid + rep * 256;
        float a = 0.f;
#pragma unroll
        for (int ch = 0; ch < kNCH; ch++)
            a += g_tpart[(size_t)(((b * kNCH + ch) * 8) + q) * kH + d];
        a += bias[d];
        a = fmaxf(a, 0.f);
        a += g_h[(size_t)row * kH + d];
        v[rep] = a; s += a; s2 += a * a;
    }
    s = wredsum(s); s2 = wredsum(s2);
    if (lane == 0){ rs[wid] = s; rs2[wid] = s2; }
    __syncthreads();
    if (tid == 0){
        float ts = 0.f, ts2 = 0.f;
#pragma unroll
        for (int w = 0; w < 8; w++){ ts += rs[w]; ts2 += rs2[w]; }
        float mu = ts / kH;
        float var = ts2 / kH - mu * mu;
        s_mu = mu; s_rstd = rsqrtf(var + 1e-5f);
    }
    __syncthreads();
    float mu = s_mu, rstd = s_rstd;
#pragma unroll
    for (int rep = 0; rep < 3; rep++){
        int d = tid + rep * 256;
        float y = (v[rep] - mu) * rstd * gam[d] + bet[d];
        g_h  [(size_t)row * kH + d] = y;
        g_haf[haf_idx(row, d)] = f2tf_f(y);
    }
}

// ---------------- launch ----------------
extern "C" void kernel_launch(void* const* d_in, const int* in_sizes, int n_in,
                              void* d_out, int out_size){
    const float* txt  = (const float*)d_in[0];
    const float* lab  = (const float*)d_in[1];
    const float* img  = (const float*)d_in[2];
    const float* W    = (const float*)d_in[3];
    const float* as   = (const float*)d_in[4];
    const float* ad   = (const float*)d_in[5];
    const float* bias = (const float*)d_in[6];
    const float* lng  = (const float*)d_in[7];
    const float* lnb  = (const float*)d_in[8];
    float* out = (float*)d_out;

    static bool attrDone = false;
    if (!attrDone){
        cudaFuncSetAttribute(k_gemm, cudaFuncAttributeMaxDynamicSharedMemorySize, kSmemBytes);
        attrDone = true;
    }

    k_wprep<<<dim3(kH / 32, kH / 32, 3), 256>>>(W);
    k_init<<<(kM * kH + 255) / 256, 256>>>(txt, lab, img);
    k_topk<<<(kB * kT) / 8, 256>>>(txt, lab, img);

    for (int li = 0; li < 3; li++){
        k_gemm<<<dim3(kMp / 128, kH / 128), 256, kSmemBytes>>>(li, as + li * kH, ad + li * kH);
        k_esred<<<(kM + 255) / 256, 256>>>();
        k_text_alpha<<<(kB * kT * kHe + 255) / 256, 256>>>();
        if (li < 2){
            k_tail_alpha<<<kB * 8, 256>>>();
            k_agg_tailm<<<dim3(kB, kHe, kNCH), 256>>>();
        }
        k_agg_text_ln<<<dim3(kB, kT / kTC), 768>>>(bias + li * kH, lng + li * kH, lnb + li * kH,
                                                   out, li == 2 ? 1 : 0);
        if (li < 2)
            k_tail_ln<<<kB * 8, 256>>>(bias + li * kH, lng + li * kH, lnb + li * kH);
    }
}

// round 13
// speedup vs baseline: 1.0611x; 1.0218x over previous
#include <cuda_runtime.h>
#include <math.h>
#include <stdint.h>

// ---------------- problem constants ----------------
constexpr int kB  = 8;
constexpr int kT  = 1024;
constexpr int kL  = 4;
constexpr int kI  = 4;
constexpr int kN  = 1032;
constexpr int kH  = 768;
constexpr int kHe = 4;
constexpr int kDh = 192;
constexpr int kM  = kB * kN;        // 8256
constexpr int kMp = 8320;           // 65*128
constexpr int kNCH = 16;
constexpr int kSPAN = 65;
constexpr int kCk = kH / 16;        // 48 K-chunks of 16
constexpr int kChunkF = 2048;       // floats per 128x16 chunk block

// ---------------- scratch ----------------
__device__ float g_h  [kMp * kH];
__device__ float g_haf[65 * kCk * kChunkF];        // A, tf32-rounded, fragment-major
__device__ float g_wbf[3 * 6 * kCk * kChunkF];     // W^T, tf32-rounded, fragment-major
__device__ float g_hw [kMp * kH];
__device__ float4 g_esp[6 * kMp];                  // per-(ntile,row) partials {es0,es1,ed0,ed1}
__device__ float g_es [kM * kHe];
__device__ float g_ed [kM * kHe];
__device__ float g_wtail[kB * kN * 32];
__device__ float g_tpart[kB * kNCH * 8 * kH];
__device__ unsigned char g_mlab[kB * kT];
__device__ unsigned char g_mimg[kB * kT];

__device__ __forceinline__ float wredsum(float v){
#pragma unroll
    for (int o = 16; o > 0; o >>= 1) v += __shfl_xor_sync(0xffffffffu, v, o);
    return v;
}
__device__ __forceinline__ float wredmax(float v){
#pragma unroll
    for (int o = 16; o > 0; o >>= 1) v = fmaxf(v, __shfl_xor_sync(0xffffffffu, v, o));
    return v;
}
__device__ __forceinline__ float f2tf_f(float x){
    uint32_t u; asm("cvt.rna.tf32.f32 %0, %1;" : "=r"(u) : "f"(x));
    return __uint_as_float(u);
}
__device__ __forceinline__ void cp16(uint32_t dst, const void* src){
    asm volatile("cp.async.cg.shared.global [%0], [%1], 16;" :: "r"(dst), "l"(src));
}

// fragment-major A index
__device__ __forceinline__ int haf_idx(int row, int d){
    int tile = row >> 7, m = row & 127;
    int g = m >> 4, rr = m & 15, r = rr & 7, p = rr >> 3;
    int ck = d >> 4, dd = d & 15;
    int h = dd >> 3, q = dd & 7, c = q & 3, chi = q >> 2;
    int slot = (h * 4 + c) ^ ((r & 1) << 2);
    return (tile * kCk + ck) * kChunkF + ((g * 8 + r) * 8 + slot) * 4 + chi * 2 + p;
}
// fragment-major B index (128-N tiles)
__device__ __forceinline__ int wbf_idx(int li, int n, int k){
    int ntile = n >> 7, nn = n & 127;
    int ck = k >> 4, dd = k & 15, c = dd & 3, j = dd >> 2;
    return ((li * 6 + ntile) * kCk + ck) * kChunkF + (nn * 4 + c) * 4 + j;
}

__device__ __forceinline__ void mma_tf32(float* c, const float4& a, float b0, float b1){
    asm volatile(
        "mma.sync.aligned.m16n8k8.row.col.f32.tf32.tf32.f32 "
        "{%0,%1,%2,%3}, {%4,%5,%6,%7}, {%8,%9}, {%0,%1,%2,%3};\n"
        : "+f"(c[0]), "+f"(c[1]), "+f"(c[2]), "+f"(c[3])
        : "r"(__float_as_uint(a.x)), "r"(__float_as_uint(a.y)),
          "r"(__float_as_uint(a.z)), "r"(__float_as_uint(a.w)),
          "r"(__float_as_uint(b0)), "r"(__float_as_uint(b1)));
}

// ---------------- 0. W -> transposed, tf32-rounded, fragment-major ----------------
__global__ __launch_bounds__(256) void k_wprep(const float* __restrict__ W){
    __shared__ float ts[32][33];
    int li = blockIdx.z;
    int k0 = blockIdx.x * 32, n0 = blockIdx.y * 32;
    int x = threadIdx.x & 31, y0 = threadIdx.x >> 5;
    const float* Wp = W + (size_t)li * kH * kH;
    for (int yy = y0; yy < 32; yy += 8)
        ts[yy][x] = Wp[(size_t)(k0 + yy) * kH + n0 + x];
    __syncthreads();
    for (int yy = y0; yy < 32; yy += 8)
        g_wbf[wbf_idx(li, n0 + yy, k0 + x)] = f2tf_f(ts[x][yy]);
}

// ---------------- 1. assemble x ----------------
__global__ __launch_bounds__(256) void k_init(const float* __restrict__ txt,
                                              const float* __restrict__ lab,
                                              const float* __restrict__ img){
    int i = blockIdx.x * 256 + threadIdx.x;
    if (i >= kM * kH) return;
    int row = i / kH, d = i % kH;
    int b = row / kN, n = row % kN;
    float v;
    if (n < kT)            v = txt[(size_t)(b * kT + n) * kH + d];
    else if (n < kT + kL)  v = lab[(size_t)(b * kL + (n - kT)) * kH + d];
    else                   v = img[(size_t)(b * kI + (n - kT - kL)) * kH + d];
    g_h  [(size_t)row * kH + d] = v;
    g_haf[haf_idx(row, d)] = f2tf_f(v);
}

// ---------------- 2. top-3-of-4 cosine masks ----------------
__global__ __launch_bounds__(256) void k_topk(const float* __restrict__ txt,
                                              const float* __restrict__ lab,
                                              const float* __restrict__ img){
    int gw   = (blockIdx.x * 256 + threadIdx.x) >> 5;
    int lane = threadIdx.x & 31;
    if (gw >= kB * kT) return;
    int b = gw / kT, t = gw % kT;
    const float* tp = txt + (size_t)(b * kT + t) * kH;
    float tn = 0.f;
    float dl[4] = {0,0,0,0}, nl[4] = {0,0,0,0};
    float di[4] = {0,0,0,0}, ni[4] = {0,0,0,0};
    for (int j = lane; j < kH; j += 32){
        float tv = tp[j];
        tn += tv * tv;
#pragma unroll
        for (int c = 0; c < 4; c++){
            float lv = lab[(size_t)(b * kL + c) * kH + j];
            dl[c] += tv * lv;  nl[c] += lv * lv;
            float iv = img[(size_t)(b * kI + c) * kH + j];
            di[c] += tv * iv;  ni[c] += iv * iv;
        }
    }
    tn = wredsum(tn);
#pragma unroll
    for (int c = 0; c < 4; c++){
        dl[c] = wredsum(dl[c]); nl[c] = wredsum(nl[c]);
        di[c] = wredsum(di[c]); ni[c] = wredsum(ni[c]);
    }
    if (lane == 0){
        float st = sqrtf(tn);
        float sl[4], si[4];
#pragma unroll
        for (int c = 0; c < 4; c++){
            sl[c] = dl[c] / fmaxf(st * sqrtf(nl[c]), 1e-8f);
            si[c] = di[c] / fmaxf(st * sqrtf(ni[c]), 1e-8f);
        }
        int bl = 0, bi = 0;
#pragma unroll
        for (int c = 1; c < 4; c++){
            if (sl[c] <= sl[bl]) bl = c;
            if (si[c] <= si[bi]) bi = c;
        }
        g_mlab[b * kT + t] = (unsigned char)(0xF ^ (1 << bl));
        g_mimg[b * kT + t] = (unsigned char)(0xF ^ (1 << bi));
    }
}

// ---------------- 3. tf32 GEMM + fused es/ed partial epilogue ----------------
constexpr int kStages = 4;
constexpr int kSmemFloats = kStages * kChunkF * 2 + 256 + 1024;
constexpr int kSmemBytes  = kSmemFloats * 4;       // 70656

__device__ __forceinline__ void fill_stage(uint32_t asB, uint32_t bsB,
                                           const float* Ac, const float* Bc, int tid){
#pragma unroll
    for (int i = 0; i < 2; i++){
        int c = tid + i * 256;
        cp16(asB + c * 16, Ac + c * 4);
        cp16(bsB + c * 16, Bc + c * 4);
    }
}

__global__ __launch_bounds__(256, 2) void k_gemm(int li, const float* __restrict__ asv,
                                                 const float* __restrict__ adv){
    extern __shared__ float sm[];
    float* As   = sm;
    float* Bs   = sm + kStages * kChunkF;
    float* as_s = sm + 2 * kStages * kChunkF;
    float* ad_s = as_s + 128;
    float4* sred = (float4*)(ad_s + 128);
    int tid  = threadIdx.x;
    int warp = tid >> 5, lane = tid & 31;
    int wr = warp & 3, wc = warp >> 2;
    int grp = lane >> 2, thr4 = lane & 3;
    const float* Ag = g_haf + (size_t)blockIdx.x * kCk * kChunkF;
    const float* Bg = g_wbf + (size_t)(li * 6 + blockIdx.y) * kCk * kChunkF;

    if (tid < 128){
        as_s[tid] = asv[blockIdx.y * 128 + tid];
        ad_s[tid] = adv[blockIdx.y * 128 + tid];
    }

    float acc[2][8][4];
#pragma unroll
    for (int mt = 0; mt < 2; mt++)
#pragma unroll
        for (int nt = 0; nt < 8; nt++)
#pragma unroll
            for (int i = 0; i < 4; i++) acc[mt][nt][i] = 0.f;

    uint32_t asBase = (uint32_t)__cvta_generic_to_shared(As);
    uint32_t bsBase = (uint32_t)__cvta_generic_to_shared(Bs);

#pragma unroll
    for (int s = 0; s < 3; s++){
        fill_stage(asBase + s * kChunkF * 4, bsBase + s * kChunkF * 4,
                   Ag + s * kChunkF, Bg + s * kChunkF, tid);
        asm volatile("cp.async.commit_group;");
    }

    int aidx[2][2];
#pragma unroll
    for (int mt = 0; mt < 2; mt++){
        int g = wr * 2 + mt;
#pragma unroll
        for (int h = 0; h < 2; h++)
            aidx[mt][h] = (g * 8 + grp) * 8 + ((h * 4 + thr4) ^ ((grp & 1) << 2));
    }
    int bidx0 = (wc * 64 + grp) * 4 + thr4;   // + nt*32

    for (int ck = 0; ck < kCk; ++ck){
        asm volatile("cp.async.wait_group 2;");
        __syncthreads();
        if (ck + 3 < kCk){
            int s = (ck + 3) & 3;
            fill_stage(asBase + s * kChunkF * 4, bsBase + s * kChunkF * 4,
                       Ag + (ck + 3) * kChunkF, Bg + (ck + 3) * kChunkF, tid);
            asm volatile("cp.async.commit_group;");
        } else {
            asm volatile("cp.async.commit_group;");
        }
        int st = ck & 3;
        const float4* Af = (const float4*)(As + st * kChunkF);
        const float4* Bf = (const float4*)(Bs + st * kChunkF);

        float4 a4[2][2];
#pragma unroll
        for (int mt = 0; mt < 2; mt++)
#pragma unroll
            for (int h = 0; h < 2; h++)
                a4[mt][h] = Af[aidx[mt][h]];
#pragma unroll
        for (int nt = 0; nt < 8; nt++){
            float4 b4 = Bf[bidx0 + nt * 32];
            mma_tf32(acc[0][nt], a4[0][0], b4.x, b4.y);
            mma_tf32(acc[1][nt], a4[1][0], b4.x, b4.y);
            mma_tf32(acc[0][nt], a4[0][1], b4.z, b4.w);
            mma_tf32(acc[1][nt], a4[1][1], b4.z, b4.w);
        }
    }

    // C store
#pragma unroll
    for (int mt = 0; mt < 2; mt++){
        int r = blockIdx.x * 128 + wr * 32 + mt * 16 + grp;
#pragma unroll
        for (int nt = 0; nt < 8; nt++){
            int cg = blockIdx.y * 128 + wc * 64 + nt * 8 + thr4 * 2;
            *(float2*)&g_hw[(size_t)r * kH + cg]       = make_float2(acc[mt][nt][0], acc[mt][nt][1]);
            *(float2*)&g_hw[(size_t)(r + 8) * kH + cg] = make_float2(acc[mt][nt][2], acc[mt][nt][3]);
        }
    }

    // fused es/ed partials
    int hl = (blockIdx.y * 128) / kDh;
    float pes[2][2][2] = {}, ped[2][2][2] = {};
#pragma unroll
    for (int mt = 0; mt < 2; mt++)
#pragma unroll
        for (int nt = 0; nt < 8; nt++){
            int cl = wc * 64 + nt * 8 + thr4 * 2;
            int head = (blockIdx.y * 128 + cl) / kDh;
            int bk = (head == hl) ? 0 : 1;
            float a0 = as_s[cl], a1 = as_s[cl + 1];
            float d0 = ad_s[cl], d1 = ad_s[cl + 1];
            pes[mt][0][bk] += acc[mt][nt][0] * a0 + acc[mt][nt][1] * a1;
            ped[mt][0][bk] += acc[mt][nt][0] * d0 + acc[mt][nt][1] * d1;
            pes[mt][1][bk] += acc[mt][nt][2] * a0 + acc[mt][nt][3] * a1;
            ped[mt][1][bk] += acc[mt][nt][2] * d0 + acc[mt][nt][3] * d1;
        }
#pragma unroll
    for (int mt = 0; mt < 2; mt++)
#pragma unroll
        for (int rh = 0; rh < 2; rh++)
#pragma unroll
            for (int bk = 0; bk < 2; bk++){
#pragma unroll
                for (int o = 1; o < 4; o <<= 1){
                    pes[mt][rh][bk] += __shfl_xor_sync(0xffffffffu, pes[mt][rh][bk], o);
                    ped[mt][rh][bk] += __shfl_xor_sync(0xffffffffu, ped[mt][rh][bk], o);
                }
            }
    if (thr4 == 0){
#pragma unroll
        for (int mt = 0; mt < 2; mt++)
#pragma unroll
            for (int rh = 0; rh < 2; rh++)
                sred[((((wc * 4 + wr) * 2 + mt) * 2 + rh) * 8) + grp] =
                    make_float4(pes[mt][rh][0], pes[mt][rh][1], ped[mt][rh][0], ped[mt][rh][1]);
    }
    __syncthreads();
    if (tid < 128){
        int twr = tid >> 5, tmt = (tid >> 4) & 1, trh = (tid >> 3) & 1, tgrp = tid & 7;
        float4 v0 = sred[((((0 * 4 + twr) * 2 + tmt) * 2 + trh) * 8) + tgrp];
        float4 v1 = sred[((((1 * 4 + twr) * 2 + tmt) * 2 + trh) * 8) + tgrp];
        float4 o = make_float4(v0.x + v1.x, v0.y + v1.y, v0.z + v1.z, v0.w + v1.w);
        g_esp[blockIdx.y * kMp + blockIdx.x * 128 + tid] = o;
    }
}

// ---------------- 3b. reduce es/ed partials across 6 N-tiles ----------------
__global__ __launch_bounds__(256) void k_esred(){
    int row = blockIdx.x * 256 + threadIdx.x;
    if (row >= kM) return;
    const int hlA[6] = {0,0,1,2,2,3};
    const int hhA[6] = {0,1,1,2,3,3};
    float es[4] = {0,0,0,0}, ed[4] = {0,0,0,0};
#pragma unroll
    for (int ty = 0; ty < 6; ty++){
        float4 v = g_esp[ty * kMp + row];
        es[hlA[ty]] += v.x; es[hhA[ty]] += v.y;
        ed[hlA[ty]] += v.z; ed[hhA[ty]] += v.w;
    }
    *(float4*)&g_es[row * kHe] = make_float4(es[0], es[1], es[2], es[3]);
    *(float4*)&g_ed[row * kHe] = make_float4(ed[0], ed[1], ed[2], ed[3]);
}

// ---------------- 5. tail softmax weights ----------------
__global__ __launch_bounds__(256) void k_tail_alpha(){
    __shared__ float ws[kN * 4];
    __shared__ float wr_[8][4];
    __shared__ float m4[4], z4[4];
    int b = blockIdx.x >> 3, q = blockIdx.x & 7;
    int tid = threadIdx.x, lane = tid & 31, wid = tid >> 5;
    int rowbase = b * kN;
    int rowdst  = rowbase + kT + q;
    float edd[4];
#pragma unroll
    for (int h = 0; h < 4; h++) edd[h] = g_ed[rowdst * kHe + h];

    float ml[4] = {-1e30f,-1e30f,-1e30f,-1e30f};
    for (int s = tid; s < kN; s += 256){
        bool inc;
        if (s < kT){
            unsigned mk = (q < 4) ? g_mlab[b * kT + s] : g_mimg[b * kT + s];
            inc = (mk >> (q & 3)) & 1;
        } else inc = true;
        if (inc){
            const float* ep = g_es + (size_t)(rowbase + s) * kHe;
#pragma unroll
            for (int h = 0; h < 4; h++){
                float e = ep[h] + edd[h];
                e = (e >= 0.f) ? e : 0.2f * e;
                ml[h] = fmaxf(ml[h], e);
            }
        }
    }
#pragma unroll
    for (int h = 0; h < 4; h++) ml[h] = wredmax(ml[h]);
    if (lane == 0){
#pragma unroll
        for (int h = 0; h < 4; h++) wr_[wid][h] = ml[h];
    }
    __syncthreads();
    if (tid < 4){
        float mm = -1e30f;
#pragma unroll
        for (int w = 0; w < 8; w++) mm = fmaxf(mm, wr_[w][tid]);
        m4[tid] = mm;
    }
    __syncthreads();

    float zl[4] = {0,0,0,0};
    for (int s = tid; s < kN; s += 256){
        bool inc;
        if (s < kT){
            unsigned mk = (q < 4) ? g_mlab[b * kT + s] : g_mimg[b * kT + s];
            inc = (mk >> (q & 3)) & 1;
        } else inc = true;
        if (inc){
            const float* ep = g_es + (size_t)(rowbase + s) * kHe;
#pragma unroll
            for (int h = 0; h < 4; h++){
                float e = ep[h] + edd[h];
                e = (e >= 0.f) ? e : 0.2f * e;
                float w = expf(e - m4[h]);
                ws[s * 4 + h] = w; zl[h] += w;
            }
        } else {
#pragma unroll
            for (int h = 0; h < 4; h++) ws[s * 4 + h] = 0.f;
        }
    }
#pragma unroll
    for (int h = 0; h < 4; h++) zl[h] = wredsum(zl[h]);
    if (lane == 0){
#pragma unroll
        for (int h = 0; h < 4; h++) wr_[wid][h] = zl[h];
    }
    __syncthreads();
    if (tid < 4){
        float ss = 0.f;
#pragma unroll
        for (int w = 0; w < 8; w++) ss += wr_[w][tid];
        z4[tid] = ss;
    }
    __syncthreads();

    float inv[4];
#pragma unroll
    for (int h = 0; h < 4; h++) inv[h] = 1.0f / z4[h];
    for (int s = tid; s < kN; s += 256){
#pragma unroll
        for (int h = 0; h < 4; h++)
            g_wtail[(size_t)(rowbase + s) * 32 + h * 8 + q] = ws[s * 4 + h] * inv[h];
    }
}

// ---------------- 6. tail aggregation partials ----------------
__global__ __launch_bounds__(256) void k_agg_tailm(){
    __shared__ float sw[kSPAN * 8];
    int b = blockIdx.x, h = blockIdx.y, ch = blockIdx.z;
    int s0 = ch * kSPAN;
    int cnt = min(kSPAN, kN - s0);
    int tid = threadIdx.x;
    for (int i = tid; i < cnt * 8; i += 256){
        int si = i >> 3, qq = i & 7;
        sw[i] = g_wtail[(size_t)(b * kN + s0 + si) * 32 + h * 8 + qq];
    }
    __syncthreads();
    if (tid < kDh){
        float acc[8] = {0,0,0,0,0,0,0,0};
        const float* hp = g_hw + (size_t)(b * kN + s0) * kH + h * kDh + tid;
#pragma unroll 4
        for (int si = 0; si < cnt; si++){
            float hv = hp[(size_t)si * kH];
            float4 w0 = *(const float4*)&sw[si * 8];
            float4 w1 = *(const float4*)&sw[si * 8 + 4];
            acc[0] += w0.x * hv; acc[1] += w0.y * hv;
            acc[2] += w0.z * hv; acc[3] += w0.w * hv;
            acc[4] += w1.x * hv; acc[5] += w1.y * hv;
            acc[6] += w1.z * hv; acc[7] += w1.w * hv;
        }
#pragma unroll
        for (int q = 0; q < 8; q++)
            g_tpart[(size_t)(((b * kNCH + ch) * 8) + q) * kH + h * kDh + tid] = acc[q];
    }
}

// ---------------- 7. text aggregate (parallel alphas) + LN ----------------
__global__ __launch_bounds__(256) void k_agg_text_ln(const float* __restrict__ bias,
                                                     const float* __restrict__ gam,
                                                     const float* __restrict__ bet,
                                                     float* __restrict__ outp, int finalFlag){
    __shared__ int   s_src[9];
    __shared__ float s_e[36], s_w[36], s_al[36];
    __shared__ float s_m[4], s_inv[4];
    __shared__ int   s_cnt;
    __shared__ float rs[8], rs2[8];
    __shared__ float s_mu, s_rstd;
    int blk = blockIdx.x;
    int b = blk / kT, t = blk % kT;
    int rowdst = b * kN + t;
    int tid = threadIdx.x;

    if (tid == 0){
        int cnt = 0;
        s_src[cnt++] = t;
        if (t > 0)      s_src[cnt++] = t - 1;
        if (t < kT - 1) s_src[cnt++] = t + 1;
        unsigned ml = g_mlab[b * kT + t], mi = g_mimg[b * kT + t];
#pragma unroll
        for (int c = 0; c < 4; c++) if ((ml >> c) & 1) s_src[cnt++] = kT + c;
#pragma unroll
        for (int c = 0; c < 4; c++) if ((mi >> c) & 1) s_src[cnt++] = kT + kL + c;
        s_cnt = cnt;
    }
    __syncthreads();
    int cnt = s_cnt;
    if (tid < 36){
        int i = tid >> 2, h = tid & 3;
        if (i < cnt){
            float e = g_es[(size_t)(b * kN + s_src[i]) * kHe + h]
                    + g_ed[(size_t)rowdst * kHe + h];
            e = (e >= 0.f) ? e : 0.2f * e;
            s_e[tid] = e;
        }
    }
    __syncthreads();
    if (tid < 4){
        float m = -1e30f;
        for (int i = 0; i < cnt; i++) m = fmaxf(m, s_e[i * 4 + tid]);
        s_m[tid] = m;
    }
    __syncthreads();
    if (tid < 36){
        int i = tid >> 2, h = tid & 3;
        if (i < cnt) s_w[tid] = expf(s_e[tid] - s_m[h]);
    }
    __syncthreads();
    if (tid < 4){
        float z = 0.f;
        for (int i = 0; i < cnt; i++) z += s_w[i * 4 + tid];
        s_inv[tid] = 1.0f / z;
    }
    __syncthreads();
    if (tid < 36){
        int i = tid >> 2, h = tid & 3;
        if (i < cnt) s_al[tid] = s_w[tid] * s_inv[h];
    }
    __syncthreads();

    int lane = tid & 31, wid = tid >> 5;
    float v[3]; float s = 0.f, s2 = 0.f;
#pragma unroll
    for (int rep = 0; rep < 3; rep++){
        int d = tid + rep * 256;
        int head = d / kDh;
        float a = 0.f;
        for (int i = 0; i < cnt; i++)
            a += s_al[i * 4 + head] * g_hw[(size_t)(b * kN + s_src[i]) * kH + d];
        a += bias[d];
        a = fmaxf(a, 0.f);
        a += g_h[(size_t)rowdst * kH + d];
        v[rep] = a; s += a; s2 += a * a;
    }
    s = wredsum(s); s2 = wredsum(s2);
    if (lane == 0){ rs[wid] = s; rs2[wid] = s2; }
    __syncthreads();
    if (tid == 0){
        float ts = 0.f, ts2 = 0.f;
#pragma unroll
        for (int w = 0; w < 8; w++){ ts += rs[w]; ts2 += rs2[w]; }
        float mu = ts / kH;
        float var = ts2 / kH - mu * mu;
        s_mu = mu; s_rstd = rsqrtf(var + 1e-5f);
    }
    __syncthreads();
    float mu = s_mu, rstd = s_rstd;
#pragma unroll
    for (int rep = 0; rep < 3; rep++){
        int d = tid + rep * 256;
        float y = (v[rep] - mu) * rstd * gam[d] + bet[d];
        if (finalFlag){
            outp[(size_t)(b * kT + t) * kH + d] = y;
        } else {
            g_h  [(size_t)rowdst * kH + d] = y;
            g_haf[haf_idx(rowdst, d)] = f2tf_f(y);
        }
    }
}

// ---------------- 8. tail rows: reduce partials + LN ----------------
__global__ __launch_bounds__(256) void k_tail_ln(const float* __restrict__ bias,
                                                 const float* __restrict__ gam,
                                                 const float* __restrict__ bet){
    int b = blockIdx.x >> 3, q = blockIdx.x & 7;
    int row = b * kN + kT + q;
    int tid = threadIdx.x, lane = tid & 31, wid = tid >> 5;
    __shared__ float rs[8], rs2[8];
    __shared__ float s_mu, s_rstd;
    float v[3]; float s = 0.f, s2 = 0.f;
#pragma unroll
    for (int rep = 0; rep < 3; rep++){
        int d = tid + rep * 256;
        float a = 0.f;
#pragma unroll
        for (int ch = 0; ch < kNCH; ch++)
            a += g_tpart[(size_t)(((b * kNCH + ch) * 8) + q) * kH + d];
        a += bias[d];
        a = fmaxf(a, 0.f);
        a += g_h[(size_t)row * kH + d];
        v[rep] = a; s += a; s2 += a * a;
    }
    s = wredsum(s); s2 = wredsum(s2);
    if (lane == 0){ rs[wid] = s; rs2[wid] = s2; }
    __syncthreads();
    if (tid == 0){
        float ts = 0.f, ts2 = 0.f;
#pragma unroll
        for (int w = 0; w < 8; w++){ ts += rs[w]; ts2 += rs2[w]; }
        float mu = ts / kH;
        float var = ts2 / kH - mu * mu;
        s_mu = mu; s_rstd = rsqrtf(var + 1e-5f);
    }
    __syncthreads();
    float mu = s_mu, rstd = s_rstd;
#pragma unroll
    for (int rep = 0; rep < 3; rep++){
        int d = tid + rep * 256;
        float y = (v[rep] - mu) * rstd * gam[d] + bet[d];
        g_h  [(size_t)row * kH + d] = y;
        g_haf[haf_idx(row, d)] = f2tf_f(y);
    }
}

// ---------------- launch (forked-stream graph) ----------------
extern "C" void kernel_launch(void* const* d_in, const int* in_sizes, int n_in,
                              void* d_out, int out_size){
    const float* txt  = (const float*)d_in[0];
    const float* lab  = (const float*)d_in[1];
    const float* img  = (const float*)d_in[2];
    const float* W    = (const float*)d_in[3];
    const float* as   = (const float*)d_in[4];
    const float* ad   = (const float*)d_in[5];
    const float* bias = (const float*)d_in[6];
    const float* lng  = (const float*)d_in[7];
    const float* lnb  = (const float*)d_in[8];
    float* out = (float*)d_out;

    static cudaStream_t s2 = nullptr;
    static cudaEvent_t evF = nullptr, evJ = nullptr;
    if (!s2){
        cudaFuncSetAttribute(k_gemm, cudaFuncAttributeMaxDynamicSharedMemorySize, kSmemBytes);
        cudaStreamCreateWithFlags(&s2, cudaStreamNonBlocking);
        cudaEventCreateWithFlags(&evF, cudaEventDisableTiming);
        cudaEventCreateWithFlags(&evJ, cudaEventDisableTiming);
    }
    cudaStream_t s0 = 0;

    // prologue: topk runs in s2 concurrent with wprep+init in s0
    cudaEventRecord(evF, s0);
    cudaStreamWaitEvent(s2, evF, 0);
    k_topk<<<(kB * kT) / 8, 256, 0, s2>>>(txt, lab, img);
    cudaEventRecord(evJ, s2);
    k_wprep<<<dim3(kH / 32, kH / 32, 3), 256, 0, s0>>>(W);
    k_init<<<(kM * kH + 255) / 256, 256, 0, s0>>>(txt, lab, img);
    cudaStreamWaitEvent(s0, evJ, 0);   // masks ready before consumers below

    for (int li = 0; li < 3; li++){
        k_gemm<<<dim3(kMp / 128, kH / 128), 256, kSmemBytes, s0>>>(li, as + li * kH, ad + li * kH);
        k_esred<<<(kM + 255) / 256, 256, 0, s0>>>();
        if (li < 2){
            // fork: tail path in s2 runs concurrent with text path in s0
            cudaEventRecord(evF, s0);
            cudaStreamWaitEvent(s2, evF, 0);
            k_tail_alpha<<<kB * 8, 256, 0, s2>>>();
            k_agg_tailm<<<dim3(kB, kHe, kNCH), 256, 0, s2>>>();
            k_tail_ln<<<kB * 8, 256, 0, s2>>>(bias + li * kH, lng + li * kH, lnb + li * kH);
            cudaEventRecord(evJ, s2);
        }
        k_agg_text_ln<<<kB * kT, 256, 0, s0>>>(bias + li * kH, lng + li * kH, lnb + li * kH,
                                               out, li == 2 ? 1 : 0);
        if (li < 2)
            cudaStreamWaitEvent(s0, evJ, 0);   // join before next layer's gemm
    }
}

// round 15
// speedup vs baseline: 1.0821x; 1.0198x over previous
#include <cuda_runtime.h>
#include <math.h>
#include <stdint.h>

// ---------------- problem constants ----------------
constexpr int kB  = 8;
constexpr int kT  = 1024;
constexpr int kL  = 4;
constexpr int kI  = 4;
constexpr int kN  = 1032;
constexpr int kH  = 768;
constexpr int kHe = 4;
constexpr int kDh = 192;
constexpr int kM  = kB * kN;        // 8256
constexpr int kMp = 8320;           // 65*128
constexpr int kNCH = 16;
constexpr int kSPAN = 65;
constexpr int kCk = kH / 16;        // 48 K-chunks of 16
constexpr int kChunkF = 2048;       // floats per 128x16 chunk block

// ---------------- scratch ----------------
__device__ float g_h  [kMp * kH];
__device__ float g_haf[65 * kCk * kChunkF];        // A, tf32-rounded, fragment-major
__device__ float g_wbf[3 * 6 * kCk * kChunkF];     // W^T, tf32-rounded, fragment-major
__device__ float g_hw [kMp * kH];
__device__ float4 g_esp[6 * kMp];                  // per-(ntile,row) partials {es0,es1,ed0,ed1}
__device__ float g_es [kM * kHe];
__device__ float g_ed [kM * kHe];
__device__ float g_wtail[kB * kN * 32];
__device__ float g_tpart[kB * kNCH * 8 * kH];
__device__ unsigned char g_mlab[kB * kT];
__device__ unsigned char g_mimg[kB * kT];

__device__ __forceinline__ float wredsum(float v){
#pragma unroll
    for (int o = 16; o > 0; o >>= 1) v += __shfl_xor_sync(0xffffffffu, v, o);
    return v;
}
__device__ __forceinline__ float wredmax(float v){
#pragma unroll
    for (int o = 16; o > 0; o >>= 1) v = fmaxf(v, __shfl_xor_sync(0xffffffffu, v, o));
    return v;
}
__device__ __forceinline__ float f2tf_f(float x){
    uint32_t u; asm("cvt.rna.tf32.f32 %0, %1;" : "=r"(u) : "f"(x));
    return __uint_as_float(u);
}
__device__ __forceinline__ void cp16(uint32_t dst, const void* src){
    asm volatile("cp.async.cg.shared.global [%0], [%1], 16;" :: "r"(dst), "l"(src));
}

// fragment-major A index
__device__ __forceinline__ int haf_idx(int row, int d){
    int tile = row >> 7, m = row & 127;
    int g = m >> 4, rr = m & 15, r = rr & 7, p = rr >> 3;
    int ck = d >> 4, dd = d & 15;
    int h = dd >> 3, q = dd & 7, c = q & 3, chi = q >> 2;
    int slot = (h * 4 + c) ^ ((r & 1) << 2);
    return (tile * kCk + ck) * kChunkF + ((g * 8 + r) * 8 + slot) * 4 + chi * 2 + p;
}
// fragment-major B index (128-N tiles)
__device__ __forceinline__ int wbf_idx(int li, int n, int k){
    int ntile = n >> 7, nn = n & 127;
    int ck = k >> 4, dd = k & 15, c = dd & 3, j = dd >> 2;
    return ((li * 6 + ntile) * kCk + ck) * kChunkF + (nn * 4 + c) * 4 + j;
}

__device__ __forceinline__ void mma_tf32(float* c, const float4& a, float b0, float b1){
    asm volatile(
        "mma.sync.aligned.m16n8k8.row.col.f32.tf32.tf32.f32 "
        "{%0,%1,%2,%3}, {%4,%5,%6,%7}, {%8,%9}, {%0,%1,%2,%3};\n"
        : "+f"(c[0]), "+f"(c[1]), "+f"(c[2]), "+f"(c[3])
        : "r"(__float_as_uint(a.x)), "r"(__float_as_uint(a.y)),
          "r"(__float_as_uint(a.z)), "r"(__float_as_uint(a.w)),
          "r"(__float_as_uint(b0)), "r"(__float_as_uint(b1)));
}

// ---------------- 0. W -> transposed, tf32-rounded, fragment-major ----------------
__global__ __launch_bounds__(256) void k_wprep(const float* __restrict__ W){
    __shared__ float ts[32][33];
    int li = blockIdx.z;
    int k0 = blockIdx.x * 32, n0 = blockIdx.y * 32;
    int x = threadIdx.x & 31, y0 = threadIdx.x >> 5;
    const float* Wp = W + (size_t)li * kH * kH;
    for (int yy = y0; yy < 32; yy += 8)
        ts[yy][x] = Wp[(size_t)(k0 + yy) * kH + n0 + x];
    __syncthreads();
    for (int yy = y0; yy < 32; yy += 8)
        g_wbf[wbf_idx(li, n0 + yy, k0 + x)] = f2tf_f(ts[x][yy]);
}

// ---------------- 1. assemble x ----------------
__global__ __launch_bounds__(256) void k_init(const float* __restrict__ txt,
                                              const float* __restrict__ lab,
                                              const float* __restrict__ img){
    int i = blockIdx.x * 256 + threadIdx.x;
    if (i >= kM * kH) return;
    int row = i / kH, d = i % kH;
    int b = row / kN, n = row % kN;
    float v;
    if (n < kT)            v = txt[(size_t)(b * kT + n) * kH + d];
    else if (n < kT + kL)  v = lab[(size_t)(b * kL + (n - kT)) * kH + d];
    else                   v = img[(size_t)(b * kI + (n - kT - kL)) * kH + d];
    g_h  [(size_t)row * kH + d] = v;
    g_haf[haf_idx(row, d)] = f2tf_f(v);
}

// ---------------- 2. top-3-of-4 cosine masks (smem-staged lab/img) ----------------
// 256 threads = 8 warps = 8 consecutive t of the SAME b (1024 blocks, b = blk/128).
__global__ __launch_bounds__(256) void k_topk(const float* __restrict__ txt,
                                              const float* __restrict__ lab,
                                              const float* __restrict__ img){
    __shared__ float s_lab[kL][kH];
    __shared__ float s_img[kI][kH];
    int tid = threadIdx.x, lane = tid & 31, wid = tid >> 5;
    int blk = blockIdx.x;
    int b = blk >> 7;                       // 128 blocks per batch sample
    int t = (blk & 127) * 8 + wid;
    // stage lab/img rows (same b for the whole block)
    for (int i = tid; i < kL * kH / 4; i += 256){
        ((float4*)&s_lab[0][0])[i] = ((const float4*)(lab + (size_t)b * kL * kH))[i];
        ((float4*)&s_img[0][0])[i] = ((const float4*)(img + (size_t)b * kI * kH))[i];
    }
    __syncthreads();

    const float* tp = txt + (size_t)(b * kT + t) * kH;
    float tn = 0.f;
    float dl[4] = {0,0,0,0}, nl[4] = {0,0,0,0};
    float di[4] = {0,0,0,0}, ni[4] = {0,0,0,0};
    for (int j = lane; j < kH; j += 32){
        float tv = tp[j];
        tn += tv * tv;
#pragma unroll
        for (int c = 0; c < 4; c++){
            float lv = s_lab[c][j];
            dl[c] += tv * lv;  nl[c] += lv * lv;
            float iv = s_img[c][j];
            di[c] += tv * iv;  ni[c] += iv * iv;
        }
    }
    tn = wredsum(tn);
#pragma unroll
    for (int c = 0; c < 4; c++){
        dl[c] = wredsum(dl[c]); nl[c] = wredsum(nl[c]);
        di[c] = wredsum(di[c]); ni[c] = wredsum(ni[c]);
    }
    if (lane == 0){
        float st = sqrtf(tn);
        float sl[4], si[4];
#pragma unroll
        for (int c = 0; c < 4; c++){
            sl[c] = dl[c] / fmaxf(st * sqrtf(nl[c]), 1e-8f);
            si[c] = di[c] / fmaxf(st * sqrtf(ni[c]), 1e-8f);
        }
        int bl = 0, bi = 0;
#pragma unroll
        for (int c = 1; c < 4; c++){
            if (sl[c] <= sl[bl]) bl = c;
            if (si[c] <= si[bi]) bi = c;
        }
        g_mlab[b * kT + t] = (unsigned char)(0xF ^ (1 << bl));
        g_mimg[b * kT + t] = (unsigned char)(0xF ^ (1 << bi));
    }
}

// ---------------- 3. tf32 GEMM + fused es/ed partial epilogue ----------------
constexpr int kStages = 4;
constexpr int kSmemFloats = kStages * kChunkF * 2 + 256 + 1024;
constexpr int kSmemBytes  = kSmemFloats * 4;       // 70656

__device__ __forceinline__ void fill_stage(uint32_t asB, uint32_t bsB,
                                           const float* Ac, const float* Bc, int tid){
#pragma unroll
    for (int i = 0; i < 2; i++){
        int c = tid + i * 256;
        cp16(asB + c * 16, Ac + c * 4);
        cp16(bsB + c * 16, Bc + c * 4);
    }
}

__global__ __launch_bounds__(256, 2) void k_gemm(int li, const float* __restrict__ asv,
                                                 const float* __restrict__ adv){
    extern __shared__ float sm[];
    float* As   = sm;
    float* Bs   = sm + kStages * kChunkF;
    float* as_s = sm + 2 * kStages * kChunkF;
    float* ad_s = as_s + 128;
    float4* sred = (float4*)(ad_s + 128);
    int tid  = threadIdx.x;
    int warp = tid >> 5, lane = tid & 31;
    int wr = warp & 3, wc = warp >> 2;
    int grp = lane >> 2, thr4 = lane & 3;
    const float* Ag = g_haf + (size_t)blockIdx.x * kCk * kChunkF;
    const float* Bg = g_wbf + (size_t)(li * 6 + blockIdx.y) * kCk * kChunkF;

    if (tid < 128){
        as_s[tid] = asv[blockIdx.y * 128 + tid];
        ad_s[tid] = adv[blockIdx.y * 128 + tid];
    }

    float acc[2][8][4];
#pragma unroll
    for (int mt = 0; mt < 2; mt++)
#pragma unroll
        for (int nt = 0; nt < 8; nt++)
#pragma unroll
            for (int i = 0; i < 4; i++) acc[mt][nt][i] = 0.f;

    uint32_t asBase = (uint32_t)__cvta_generic_to_shared(As);
    uint32_t bsBase = (uint32_t)__cvta_generic_to_shared(Bs);

#pragma unroll
    for (int s = 0; s < 3; s++){
        fill_stage(asBase + s * kChunkF * 4, bsBase + s * kChunkF * 4,
                   Ag + s * kChunkF, Bg + s * kChunkF, tid);
        asm volatile("cp.async.commit_group;");
    }

    int aidx[2][2];
#pragma unroll
    for (int mt = 0; mt < 2; mt++){
        int g = wr * 2 + mt;
#pragma unroll
        for (int h = 0; h < 2; h++)
            aidx[mt][h] = (g * 8 + grp) * 8 + ((h * 4 + thr4) ^ ((grp & 1) << 2));
    }
    int bidx0 = (wc * 64 + grp) * 4 + thr4;   // + nt*32

    for (int ck = 0; ck < kCk; ++ck){
        asm volatile("cp.async.wait_group 2;");
        __syncthreads();
        if (ck + 3 < kCk){
            int s = (ck + 3) & 3;
            fill_stage(asBase + s * kChunkF * 4, bsBase + s * kChunkF * 4,
                       Ag + (ck + 3) * kChunkF, Bg + (ck + 3) * kChunkF, tid);
            asm volatile("cp.async.commit_group;");
        } else {
            asm volatile("cp.async.commit_group;");
        }
        int st = ck & 3;
        const float4* Af = (const float4*)(As + st * kChunkF);
        const float4* Bf = (const float4*)(Bs + st * kChunkF);

        float4 a4[2][2];
#pragma unroll
        for (int mt = 0; mt < 2; mt++)
#pragma unroll
            for (int h = 0; h < 2; h++)
                a4[mt][h] = Af[aidx[mt][h]];
#pragma unroll
        for (int nt = 0; nt < 8; nt++){
            float4 b4 = Bf[bidx0 + nt * 32];
            mma_tf32(acc[0][nt], a4[0][0], b4.x, b4.y);
            mma_tf32(acc[1][nt], a4[1][0], b4.x, b4.y);
            mma_tf32(acc[0][nt], a4[0][1], b4.z, b4.w);
            mma_tf32(acc[1][nt], a4[1][1], b4.z, b4.w);
        }
    }

    // C store
#pragma unroll
    for (int mt = 0; mt < 2; mt++){
        int r = blockIdx.x * 128 + wr * 32 + mt * 16 + grp;
#pragma unroll
        for (int nt = 0; nt < 8; nt++){
            int cg = blockIdx.y * 128 + wc * 64 + nt * 8 + thr4 * 2;
            *(float2*)&g_hw[(size_t)r * kH + cg]       = make_float2(acc[mt][nt][0], acc[mt][nt][1]);
            *(float2*)&g_hw[(size_t)(r + 8) * kH + cg] = make_float2(acc[mt][nt][2], acc[mt][nt][3]);
        }
    }

    // fused es/ed partials
    int hl = (blockIdx.y * 128) / kDh;
    float pes[2][2][2] = {}, ped[2][2][2] = {};
#pragma unroll
    for (int mt = 0; mt < 2; mt++)
#pragma unroll
        for (int nt = 0; nt < 8; nt++){
            int cl = wc * 64 + nt * 8 + thr4 * 2;
            int head = (blockIdx.y * 128 + cl) / kDh;
            int bk = (head == hl) ? 0 : 1;
            float a0 = as_s[cl], a1 = as_s[cl + 1];
            float d0 = ad_s[cl], d1 = ad_s[cl + 1];
            pes[mt][0][bk] += acc[mt][nt][0] * a0 + acc[mt][nt][1] * a1;
            ped[mt][0][bk] += acc[mt][nt][0] * d0 + acc[mt][nt][1] * d1;
            pes[mt][1][bk] += acc[mt][nt][2] * a0 + acc[mt][nt][3] * a1;
            ped[mt][1][bk] += acc[mt][nt][2] * d0 + acc[mt][nt][3] * d1;
        }
#pragma unroll
    for (int mt = 0; mt < 2; mt++)
#pragma unroll
        for (int rh = 0; rh < 2; rh++)
#pragma unroll
            for (int bk = 0; bk < 2; bk++){
#pragma unroll
                for (int o = 1; o < 4; o <<= 1){
                    pes[mt][rh][bk] += __shfl_xor_sync(0xffffffffu, pes[mt][rh][bk], o);
                    ped[mt][rh][bk] += __shfl_xor_sync(0xffffffffu, ped[mt][rh][bk], o);
                }
            }
    if (thr4 == 0){
#pragma unroll
        for (int mt = 0; mt < 2; mt++)
#pragma unroll
            for (int rh = 0; rh < 2; rh++)
                sred[((((wc * 4 + wr) * 2 + mt) * 2 + rh) * 8) + grp] =
                    make_float4(pes[mt][rh][0], pes[mt][rh][1], ped[mt][rh][0], ped[mt][rh][1]);
    }
    __syncthreads();
    if (tid < 128){
        int twr = tid >> 5, tmt = (tid >> 4) & 1, trh = (tid >> 3) & 1, tgrp = tid & 7;
        float4 v0 = sred[((((0 * 4 + twr) * 2 + tmt) * 2 + trh) * 8) + tgrp];
        float4 v1 = sred[((((1 * 4 + twr) * 2 + tmt) * 2 + trh) * 8) + tgrp];
        float4 o = make_float4(v0.x + v1.x, v0.y + v1.y, v0.z + v1.z, v0.w + v1.w);
        g_esp[blockIdx.y * kMp + blockIdx.x * 128 + tid] = o;
    }
}

// ---------------- 3b. reduce es/ed partials across 6 N-tiles ----------------
__global__ __launch_bounds__(256) void k_esred(){
    int row = blockIdx.x * 256 + threadIdx.x;
    if (row >= kM) return;
    const int hlA[6] = {0,0,1,2,2,3};
    const int hhA[6] = {0,1,1,2,3,3};
    float es[4] = {0,0,0,0}, ed[4] = {0,0,0,0};
#pragma unroll
    for (int ty = 0; ty < 6; ty++){
        float4 v = g_esp[ty * kMp + row];
        es[hlA[ty]] += v.x; es[hhA[ty]] += v.y;
        ed[hlA[ty]] += v.z; ed[hhA[ty]] += v.w;
    }
    *(float4*)&g_es[row * kHe] = make_float4(es[0], es[1], es[2], es[3]);
    *(float4*)&g_ed[row * kHe] = make_float4(ed[0], ed[1], ed[2], ed[3]);
}

// ---------------- 5. tail softmax weights ----------------
__global__ __launch_bounds__(256) void k_tail_alpha(){
    __shared__ float ws[kN * 4];
    __shared__ float wr_[8][4];
    __shared__ float m4[4], z4[4];
    int b = blockIdx.x >> 3, q = blockIdx.x & 7;
    int tid = threadIdx.x, lane = tid & 31, wid = tid >> 5;
    int rowbase = b * kN;
    int rowdst  = rowbase + kT + q;
    float edd[4];
#pragma unroll
    for (int h = 0; h < 4; h++) edd[h] = g_ed[rowdst * kHe + h];

    float ml[4] = {-1e30f,-1e30f,-1e30f,-1e30f};
    for (int s = tid; s < kN; s += 256){
        bool inc;
        if (s < kT){
            unsigned mk = (q < 4) ? g_mlab[b * kT + s] : g_mimg[b * kT + s];
            inc = (mk >> (q & 3)) & 1;
        } else inc = true;
        if (inc){
            const float* ep = g_es + (size_t)(rowbase + s) * kHe;
#pragma unroll
            for (int h = 0; h < 4; h++){
                float e = ep[h] + edd[h];
                e = (e >= 0.f) ? e : 0.2f * e;
                ml[h] = fmaxf(ml[h], e);
            }
        }
    }
#pragma unroll
    for (int h = 0; h < 4; h++) ml[h] = wredmax(ml[h]);
    if (lane == 0){
#pragma unroll
        for (int h = 0; h < 4; h++) wr_[wid][h] = ml[h];
    }
    __syncthreads();
    if (tid < 4){
        float mm = -1e30f;
#pragma unroll
        for (int w = 0; w < 8; w++) mm = fmaxf(mm, wr_[w][tid]);
        m4[tid] = mm;
    }
    __syncthreads();

    float zl[4] = {0,0,0,0};
    for (int s = tid; s < kN; s += 256){
        bool inc;
        if (s < kT){
            unsigned mk = (q < 4) ? g_mlab[b * kT + s] : g_mimg[b * kT + s];
            inc = (mk >> (q & 3)) & 1;
        } else inc = true;
        if (inc){
            const float* ep = g_es + (size_t)(rowbase + s) * kHe;
#pragma unroll
            for (int h = 0; h < 4; h++){
                float e = ep[h] + edd[h];
                e = (e >= 0.f) ? e : 0.2f * e;
                float w = expf(e - m4[h]);
                ws[s * 4 + h] = w; zl[h] += w;
            }
        } else {
#pragma unroll
            for (int h = 0; h < 4; h++) ws[s * 4 + h] = 0.f;
        }
    }
#pragma unroll
    for (int h = 0; h < 4; h++) zl[h] = wredsum(zl[h]);
    if (lane == 0){
#pragma unroll
        for (int h = 0; h < 4; h++) wr_[wid][h] = zl[h];
    }
    __syncthreads();
    if (tid < 4){
        float ss = 0.f;
#pragma unroll
        for (int w = 0; w < 8; w++) ss += wr_[w][tid];
        z4[tid] = ss;
    }
    __syncthreads();

    float inv[4];
#pragma unroll
    for (int h = 0; h < 4; h++) inv[h] = 1.0f / z4[h];
    for (int s = tid; s < kN; s += 256){
#pragma unroll
        for (int h = 0; h < 4; h++)
            g_wtail[(size_t)(rowbase + s) * 32 + h * 8 + q] = ws[s * 4 + h] * inv[h];
    }
}

// ---------------- 6. tail aggregation partials ----------------
__global__ __launch_bounds__(256) void k_agg_tailm(){
    __shared__ float sw[kSPAN * 8];
    int b = blockIdx.x, h = blockIdx.y, ch = blockIdx.z;
    int s0 = ch * kSPAN;
    int cnt = min(kSPAN, kN - s0);
    int tid = threadIdx.x;
    for (int i = tid; i < cnt * 8; i += 256){
        int si = i >> 3, qq = i & 7;
        sw[i] = g_wtail[(size_t)(b * kN + s0 + si) * 32 + h * 8 + qq];
    }
    __syncthreads();
    if (tid < kDh){
        float acc[8] = {0,0,0,0,0,0,0,0};
        const float* hp = g_hw + (size_t)(b * kN + s0) * kH + h * kDh + tid;
#pragma unroll 4
        for (int si = 0; si < cnt; si++){
            float hv = hp[(size_t)si * kH];
            float4 w0 = *(const float4*)&sw[si * 8];
            float4 w1 = *(const float4*)&sw[si * 8 + 4];
            acc[0] += w0.x * hv; acc[1] += w0.y * hv;
            acc[2] += w0.z * hv; acc[3] += w0.w * hv;
            acc[4] += w1.x * hv; acc[5] += w1.y * hv;
            acc[6] += w1.z * hv; acc[7] += w1.w * hv;
        }
#pragma unroll
        for (int q = 0; q < 8; q++)
            g_tpart[(size_t)(((b * kNCH + ch) * 8) + q) * kH + h * kDh + tid] = acc[q];
    }
}

// ---------------- 7. text aggregate (parallel alphas) + LN ----------------
__global__ __launch_bounds__(256) void k_agg_text_ln(const float* __restrict__ bias,
                                                     const float* __restrict__ gam,
                                                     const float* __restrict__ bet,
                                                     float* __restrict__ outp, int finalFlag){
    __shared__ int   s_src[9];
    __shared__ float s_e[36], s_w[36], s_al[36];
    __shared__ float s_m[4], s_inv[4];
    __shared__ int   s_cnt;
    __shared__ float rs[8], rs2[8];
    __shared__ float s_mu, s_rstd;
    int blk = blockIdx.x;
    int b = blk / kT, t = blk % kT;
    int rowdst = b * kN + t;
    int tid = threadIdx.x;

    if (tid == 0){
        int cnt = 0;
        s_src[cnt++] = t;
        if (t > 0)      s_src[cnt++] = t - 1;
        if (t < kT - 1) s_src[cnt++] = t + 1;
        unsigned ml = g_mlab[b * kT + t], mi = g_mimg[b * kT + t];
#pragma unroll
        for (int c = 0; c < 4; c++) if ((ml >> c) & 1) s_src[cnt++] = kT + c;
#pragma unroll
        for (int c = 0; c < 4; c++) if ((mi >> c) & 1) s_src[cnt++] = kT + kL + c;
        s_cnt = cnt;
    }
    __syncthreads();
    int cnt = s_cnt;
    if (tid < 36){
        int i = tid >> 2, h = tid & 3;
        if (i < cnt){
            float e = g_es[(size_t)(b * kN + s_src[i]) * kHe + h]
                    + g_ed[(size_t)rowdst * kHe + h];
            e = (e >= 0.f) ? e : 0.2f * e;
            s_e[tid] = e;
        }
    }
    __syncthreads();
    if (tid < 4){
        float m = -1e30f;
        for (int i = 0; i < cnt; i++) m = fmaxf(m, s_e[i * 4 + tid]);
        s_m[tid] = m;
    }
    __syncthreads();
    if (tid < 36){
        int i = tid >> 2, h = tid & 3;
        if (i < cnt) s_w[tid] = expf(s_e[tid] - s_m[h]);
    }
    __syncthreads();
    if (tid < 4){
        float z = 0.f;
        for (int i = 0; i < cnt; i++) z += s_w[i * 4 + tid];
        s_inv[tid] = 1.0f / z;
    }
    __syncthreads();
    if (tid < 36){
        int i = tid >> 2, h = tid & 3;
        if (i < cnt) s_al[tid] = s_w[tid] * s_inv[h];
    }
    __syncthreads();

    int lane = tid & 31, wid = tid >> 5;
    float v[3]; float s = 0.f, s2 = 0.f;
#pragma unroll
    for (int rep = 0; rep < 3; rep++){
        int d = tid + rep * 256;
        int head = d / kDh;
        float a = 0.f;
        for (int i = 0; i < cnt; i++)
            a += s_al[i * 4 + head] * g_hw[(size_t)(b * kN + s_src[i]) * kH + d];
        a += bias[d];
        a = fmaxf(a, 0.f);
        a += g_h[(size_t)rowdst * kH + d];
        v[rep] = a; s += a; s2 += a * a;
    }
    s = wredsum(s); s2 = wredsum(s2);
    if (lane == 0){ rs[wid] = s; rs2[wid] = s2; }
    __syncthreads();
    if (tid == 0){
        float ts = 0.f, ts2 = 0.f;
#pragma unroll
        for (int w = 0; w < 8; w++){ ts += rs[w]; ts2 += rs2[w]; }
        float mu = ts / kH;
        float var = ts2 / kH - mu * mu;
        s_mu = mu; s_rstd = rsqrtf(var + 1e-5f);
    }
    __syncthreads();
    float mu = s_mu, rstd = s_rstd;
#pragma unroll
    for (int rep = 0; rep < 3; rep++){
        int d = tid + rep * 256;
        float y = (v[rep] - mu) * rstd * gam[d] + bet[d];
        if (finalFlag){
            outp[(size_t)(b * kT + t) * kH + d] = y;
        } else {
            g_h  [(size_t)rowdst * kH + d] = y;
            g_haf[haf_idx(rowdst, d)] = f2tf_f(y);
        }
    }
}

// ---------------- 8. tail rows: reduce partials + LN ----------------
__global__ __launch_bounds__(256) void k_tail_ln(const float* __restrict__ bias,
                                                 const float* __restrict__ gam,
                                                 const float* __restrict__ bet){
    int b = blockIdx.x >> 3, q = blockIdx.x & 7;
    int row = b * kN + kT + q;
    int tid = threadIdx.x, lane = tid & 31, wid = tid >> 5;
    __shared__ float rs[8], rs2[8];
    __shared__ float s_mu, s_rstd;
    float v[3]; float s = 0.f, s2 = 0.f;
#pragma unroll
    for (int rep = 0; rep < 3; rep++){
        int d = tid + rep * 256;
        float a = 0.f;
#pragma unroll
        for (int ch = 0; ch < kNCH; ch++)
            a += g_tpart[(size_t)(((b * kNCH + ch) * 8) + q) * kH + d];
        a += bias[d];
        a = fmaxf(a, 0.f);
        a += g_h[(size_t)row * kH + d];
        v[rep] = a; s += a; s2 += a * a;
    }
    s = wredsum(s); s2 = wredsum(s2);
    if (lane == 0){ rs[wid] = s; rs2[wid] = s2; }
    __syncthreads();
    if (tid == 0){
        float ts = 0.f, ts2 = 0.f;
#pragma unroll
        for (int w = 0; w < 8; w++){ ts += rs[w]; ts2 += rs2[w]; }
        float mu = ts / kH;
        float var = ts2 / kH - mu * mu;
        s_mu = mu; s_rstd = rsqrtf(var + 1e-5f);
    }
    __syncthreads();
    float mu = s_mu, rstd = s_rstd;
#pragma unroll
    for (int rep = 0; rep < 3; rep++){
        int d = tid + rep * 256;
        float y = (v[rep] - mu) * rstd * gam[d] + bet[d];
        g_h  [(size_t)row * kH + d] = y;
        g_haf[haf_idx(row, d)] = f2tf_f(y);
    }
}

// ---------------- launch ----------------
extern "C" void kernel_launch(void* const* d_in, const int* in_sizes, int n_in,
                              void* d_out, int out_size){
    const float* txt  = (const float*)d_in[0];
    const float* lab  = (const float*)d_in[1];
    const float* img  = (const float*)d_in[2];
    const float* W    = (const float*)d_in[3];
    const float* as   = (const float*)d_in[4];
    const float* ad   = (const float*)d_in[5];
    const float* bias = (const float*)d_in[6];
    const float* lng  = (const float*)d_in[7];
    const float* lnb  = (const float*)d_in[8];
    float* out = (float*)d_out;

    static bool attrDone = false;
    if (!attrDone){
        cudaFuncSetAttribute(k_gemm, cudaFuncAttributeMaxDynamicSharedMemorySize, kSmemBytes);
        attrDone = true;
    }

    k_wprep<<<dim3(kH / 32, kH / 32, 3), 256>>>(W);
    k_init<<<(kM * kH + 255) / 256, 256>>>(txt, lab, img);
    k_topk<<<kB * kT / 8, 256>>>(txt, lab, img);

    for (int li = 0; li < 3; li++){
        k_gemm<<<dim3(kMp / 128, kH / 128), 256, kSmemBytes>>>(li, as + li * kH, ad + li * kH);
        k_esred<<<(kM + 255) / 256, 256>>>();
        if (li < 2){
            k_tail_alpha<<<kB * 8, 256>>>();
            k_agg_tailm<<<dim3(kB, kHe, kNCH), 256>>>();
        }
        k_agg_text_ln<<<kB * kT, 256>>>(bias + li * kH, lng + li * kH, lnb + li * kH,
                                        out, li == 2 ? 1 : 0);
        if (li < 2)
            k_tail_ln<<<kB * 8, 256>>>(bias + li * kH, lng + li * kH, lnb + li * kH);
    }
}